// round 1
// baseline (speedup 1.0000x reference)
#include <cuda_runtime.h>
#include <cstdint>

// ---------------------------------------------------------------------------
// Problem constants
// ---------------------------------------------------------------------------
#define BIMG   64
#define HWDIM  56
#define CCH    96
#define NHEADS 3
#define DHEAD  32
#define WIN    7
#define SHIFTW 3
#define NTOK   49                 // tokens per window
#define NWIN   64                 // windows per image (8x8)
#define NWTOT  (BIMG * NWIN)      // 4096 windows total
#define TOKENS (NWTOT * NTOK)     // 200704 tokens total
#define MLPH   384
#define METAH  128
#define LN_EPS 1e-5f

// ---------------------------------------------------------------------------
// Device scratch (static allocation: cudaMalloc is forbidden)
// ---------------------------------------------------------------------------
__device__ float g_h   [(size_t)TOKENS * CCH];       // LN1'd, shifted+windowed tokens
__device__ float g_q   [(size_t)NWTOT * NHEADS * NTOK * DHEAD];
__device__ float g_k   [(size_t)NWTOT * NHEADS * NTOK * DHEAD];
__device__ float g_v   [(size_t)NWTOT * NHEADS * NTOK * DHEAD];
__device__ float g_o   [(size_t)TOKENS * CCH];       // attention output (window layout)
__device__ float g_ln2 [(size_t)TOKENS * CCH];       // LN2(x2)
__device__ float g_hid [(size_t)TOKENS * MLPH];      // gelu(fc1)
__device__ float g_bias[NHEADS * NTOK * NTOK];       // log-CPB bias table
__device__ float g_pq[1024], g_pk[1024];             // partial sums (deterministic)
__device__ float g_sumq, g_sumk;

// ---------------------------------------------------------------------------
// Helpers
// ---------------------------------------------------------------------------
__device__ __forceinline__ float warp_sum(float v) {
#pragma unroll
    for (int o = 16; o; o >>= 1) v += __shfl_xor_sync(0xffffffffu, v, o);
    return v;
}
__device__ __forceinline__ float warp_max(float v) {
#pragma unroll
    for (int o = 16; o; o >>= 1) v = fmaxf(v, __shfl_xor_sync(0xffffffffu, v, o));
    return v;
}
__device__ __forceinline__ float gelu_tanh(float x) {
    // jax.nn.gelu default (approximate=True)
    float x3 = x * x * x;
    return 0.5f * x * (1.f + tanhf(0.7978845608028654f * (x + 0.044715f * x3)));
}

// ---------------------------------------------------------------------------
// Prep: log-CPB bias table (3 x 49 x 49) from the meta-MLP. 2401 threads.
// ---------------------------------------------------------------------------
__global__ void prep_kernel(const float* __restrict__ w1, const float* __restrict__ b1,
                            const float* __restrict__ w2, const float* __restrict__ b2) {
    int idx = blockIdx.x * blockDim.x + threadIdx.x;
    if (idx >= NTOK * NTOK) return;
    int i = idx / NTOK, j = idx % NTOK;
    float d0 = (float)(i / WIN - j / WIN);
    float d1 = (float)(i % WIN - j % WIN);
    float r0 = copysignf(log1pf(fabsf(d0)), d0);
    float r1 = copysignf(log1pf(fabsf(d1)), d1);
    float a0 = 0.f, a1 = 0.f, a2 = 0.f;
#pragma unroll 4
    for (int m = 0; m < METAH; m++) {
        float hsum = r0 * w1[m] + r1 * w1[METAH + m] + b1[m];
        float gl = gelu_tanh(hsum);
        a0 += gl * w2[m * 3 + 0];
        a1 += gl * w2[m * 3 + 1];
        a2 += gl * w2[m * 3 + 2];
    }
    g_bias[0 * NTOK * NTOK + idx] = a0 + b2[0];
    g_bias[1 * NTOK * NTOK + idx] = a1 + b2[1];
    g_bias[2 * NTOK * NTOK + idx] = a2 + b2[2];
}

// ---------------------------------------------------------------------------
// LN1 + cyclic shift + window partition.  One warp per token.
// Token (w, n): source pixel = ((wy*7 + r + 3) % 56, (wx*7 + c + 3) % 56)
// ---------------------------------------------------------------------------
__global__ __launch_bounds__(256) void ln1_gather_kernel(const float* __restrict__ x,
                                                         const float* __restrict__ g,
                                                         const float* __restrict__ b) {
    int warp = (blockIdx.x * blockDim.x + threadIdx.x) >> 5;
    int lane = threadIdx.x & 31;
    if (warp >= TOKENS) return;
    int w = warp / NTOK, n = warp % NTOK;
    int bimg = w >> 6, wi = w & 63;
    int Y = (wi >> 3) * WIN + n / WIN + SHIFTW; if (Y >= HWDIM) Y -= HWDIM;
    int X = (wi & 7)  * WIN + n % WIN + SHIFTW; if (X >= HWDIM) X -= HWDIM;
    const float* src = x + ((size_t)bimg * (HWDIM * HWDIM) + Y * HWDIM + X) * CCH;
    float v0 = src[lane], v1 = src[lane + 32], v2 = src[lane + 64];
    float s  = warp_sum(v0 + v1 + v2);
    float sq = warp_sum(v0 * v0 + v1 * v1 + v2 * v2);
    float mean = s * (1.f / CCH);
    float var  = sq * (1.f / CCH) - mean * mean;
    float inv  = rsqrtf(var + LN_EPS);
    float* dst = g_h + (size_t)warp * CCH;
    dst[lane]      = (v0 - mean) * inv * g[lane]      + b[lane];
    dst[lane + 32] = (v1 - mean) * inv * g[lane + 32] + b[lane + 32];
    dst[lane + 64] = (v2 - mean) * inv * g[lane + 64] + b[lane + 64];
}

// ---------------------------------------------------------------------------
// LN2 over x2 (= d_out after proj kernel), linear token layout.
// ---------------------------------------------------------------------------
__global__ __launch_bounds__(256) void ln2_kernel(const float* __restrict__ x2,
                                                  const float* __restrict__ g,
                                                  const float* __restrict__ b) {
    int warp = (blockIdx.x * blockDim.x + threadIdx.x) >> 5;
    int lane = threadIdx.x & 31;
    if (warp >= TOKENS) return;
    const float* src = x2 + (size_t)warp * CCH;
    float v0 = src[lane], v1 = src[lane + 32], v2 = src[lane + 64];
    float s  = warp_sum(v0 + v1 + v2);
    float sq = warp_sum(v0 * v0 + v1 * v1 + v2 * v2);
    float mean = s * (1.f / CCH);
    float var  = sq * (1.f / CCH) - mean * mean;
    float inv  = rsqrtf(var + LN_EPS);
    float* dst = g_ln2 + (size_t)warp * CCH;
    dst[lane]      = (v0 - mean) * inv * g[lane]      + b[lane];
    dst[lane + 32] = (v1 - mean) * inv * g[lane + 32] + b[lane + 32];
    dst[lane + 64] = (v2 - mean) * inv * g[lane + 64] + b[lane + 64];
}

// ---------------------------------------------------------------------------
// Tiled fp32 GEMM, BM=64, BN=48, BK=96, 256 threads, 4x3 register tile.
// EPI 0: qkv  (A=g_h,   N=288)  -> scatter into g_q/g_k/g_v (+qkv_b)
// EPI 1: proj (A=g_o,   N=96)   -> d_out = x + window_reverse(proj)
// EPI 2: fc1  (A=g_ln2, N=384)  -> g_hid = gelu(.)
// EPI 3: fc2  (A=g_hid, N=96, K=384) -> d_out += .
// ---------------------------------------------------------------------------
template <int EPI>
__global__ __launch_bounds__(256) void gemm_kernel(const float* __restrict__ Bw,
                                                   const float* __restrict__ bias,
                                                   const float* __restrict__ Xres,
                                                   float* __restrict__ out) {
    constexpr int N   = (EPI == 0) ? 288 : (EPI == 2) ? 384 : 96;
    constexpr int KT  = (EPI == 3) ? 384 : 96;
    constexpr int NCH = KT / 96;
    const float* __restrict__ A =
        (EPI == 0) ? g_h : (EPI == 1) ? g_o : (EPI == 2) ? g_ln2 : g_hid;

    __shared__ float sA[64 * 97];
    __shared__ float sB[96 * 48];

    const int tid = threadIdx.x;
    const int tc = tid & 15;          // column group: cols tc*3 .. tc*3+2
    const int tr = tid >> 4;          // row group:    rows tr*4 .. tr*4+3
    const int m0 = blockIdx.x * 64;
    const int n0 = blockIdx.y * 48;

    float acc[4][3];
#pragma unroll
    for (int i = 0; i < 4; i++)
#pragma unroll
        for (int j = 0; j < 3; j++) acc[i][j] = 0.f;

    for (int kc = 0; kc < NCH; kc++) {
#pragma unroll
        for (int l = 0; l < 24; l++) {                 // 64*96 = 24*256
            int idx = tid + l * 256;
            int r = idx / 96, k = idx - r * 96;
            sA[r * 97 + k] = A[(size_t)(m0 + r) * KT + kc * 96 + k];
        }
#pragma unroll
        for (int l = 0; l < 18; l++) {                 // 96*48 = 18*256
            int idx = tid + l * 256;
            int k = idx / 48;
            sB[idx] = Bw[(size_t)(kc * 96 + k) * N + n0 + (idx - k * 48)];
        }
        __syncthreads();
#pragma unroll 8
        for (int k = 0; k < 96; k++) {
            float a0 = sA[(tr * 4 + 0) * 97 + k];
            float a1 = sA[(tr * 4 + 1) * 97 + k];
            float a2 = sA[(tr * 4 + 2) * 97 + k];
            float a3 = sA[(tr * 4 + 3) * 97 + k];
            float b0 = sB[k * 48 + tc * 3 + 0];
            float b1 = sB[k * 48 + tc * 3 + 1];
            float b2 = sB[k * 48 + tc * 3 + 2];
            acc[0][0] += a0 * b0; acc[0][1] += a0 * b1; acc[0][2] += a0 * b2;
            acc[1][0] += a1 * b0; acc[1][1] += a1 * b1; acc[1][2] += a1 * b2;
            acc[2][0] += a2 * b0; acc[2][1] += a2 * b1; acc[2][2] += a2 * b2;
            acc[3][0] += a3 * b0; acc[3][1] += a3 * b1; acc[3][2] += a3 * b2;
        }
        __syncthreads();
    }

#pragma unroll
    for (int i = 0; i < 4; i++) {
        int row = m0 + tr * 4 + i;                      // < 200704 always
#pragma unroll
        for (int j = 0; j < 3; j++) {
            int col = n0 + tc * 3 + j;
            float val = acc[i][j];
            if (EPI == 0) {
                val += bias[col];
                int s  = col / 96;
                int hd = (col % 96) / DHEAD;
                int dd = col & (DHEAD - 1);
                int w  = row / NTOK, n = row % NTOK;
                size_t oi = ((size_t)(w * NHEADS + hd) * NTOK + n) * DHEAD + dd;
                float* dst = (s == 0) ? g_q : (s == 1) ? g_k : g_v;
                dst[oi] = val;
            } else if (EPI == 1) {
                val += bias[col];
                int w = row / NTOK, n = row % NTOK;
                int b = w >> 6, wi = w & 63;
                int Y = (wi >> 3) * WIN + n / WIN + SHIFTW; if (Y >= HWDIM) Y -= HWDIM;
                int X = (wi & 7)  * WIN + n % WIN + SHIFTW; if (X >= HWDIM) X -= HWDIM;
                size_t oi = ((size_t)b * (HWDIM * HWDIM) + Y * HWDIM + X) * CCH + col;
                out[oi] = Xres[oi] + val;               // x2 = shortcut + o
            } else if (EPI == 2) {
                g_hid[(size_t)row * MLPH + col] = gelu_tanh(val + bias[col]);
            } else {
                out[(size_t)row * CCH + col] += val + bias[col];   // final += m
            }
        }
    }
}

// ---------------------------------------------------------------------------
// Deterministic global sum-of-squares of q and k (two stages, no atomics)
// ---------------------------------------------------------------------------
__global__ __launch_bounds__(256) void redsum_kernel() {
    const size_t n = (size_t)TOKENS * CCH;
    float lq = 0.f, lk = 0.f;
    for (size_t i = (size_t)blockIdx.x * 256 + threadIdx.x; i < n; i += (size_t)1024 * 256) {
        float a = g_q[i]; lq += a * a;
        float b = g_k[i]; lk += b * b;
    }
    lq = warp_sum(lq); lk = warp_sum(lk);
    __shared__ float sq8[8], sk8[8];
    if ((threadIdx.x & 31) == 0) { sq8[threadIdx.x >> 5] = lq; sk8[threadIdx.x >> 5] = lk; }
    __syncthreads();
    if (threadIdx.x == 0) {
        float a = 0.f, b = 0.f;
#pragma unroll
        for (int i = 0; i < 8; i++) { a += sq8[i]; b += sk8[i]; }
        g_pq[blockIdx.x] = a; g_pk[blockIdx.x] = b;
    }
}
__global__ __launch_bounds__(256) void redfinal_kernel() {
    float lq = 0.f, lk = 0.f;
    for (int i = threadIdx.x; i < 1024; i += 256) { lq += g_pq[i]; lk += g_pk[i]; }
    lq = warp_sum(lq); lk = warp_sum(lk);
    __shared__ float sq8[8], sk8[8];
    if ((threadIdx.x & 31) == 0) { sq8[threadIdx.x >> 5] = lq; sk8[threadIdx.x >> 5] = lk; }
    __syncthreads();
    if (threadIdx.x == 0) {
        float a = 0.f, b = 0.f;
#pragma unroll
        for (int i = 0; i < 8; i++) { a += sq8[i]; b += sk8[i]; }
        g_sumq = a; g_sumk = b;
    }
}

// ---------------------------------------------------------------------------
// Attention: one block per (window, head). S = qk^T, scale+bias+mask,
// softmax, O = S v.  smem tiles padded for conflict-free access.
// ---------------------------------------------------------------------------
__global__ __launch_bounds__(256) void attn_kernel(const float* __restrict__ tau) {
    __shared__ float sq[64 * 33];
    __shared__ float sk[64 * 33];
    __shared__ float sv[49 * 36];
    __shared__ float ss[49 * 49];
    __shared__ int   sreg[49];

    const int blk = blockIdx.x;
    const int w = blk / NHEADS, hd = blk % NHEADS;
    const int tid = threadIdx.x;
    const size_t base = (size_t)(w * NHEADS + hd) * NTOK * DHEAD;

    // load q, k (zero-padded to 64 rows), v
    for (int idx = tid; idx < 64 * DHEAD; idx += 256) {
        int n = idx >> 5, dd = idx & 31;
        float qv = 0.f, kv = 0.f;
        if (n < NTOK) { qv = g_q[base + idx]; kv = g_k[base + idx]; }
        sq[n * 33 + dd] = qv;
        sk[n * 33 + dd] = kv;
    }
    for (int idx = tid; idx < NTOK * DHEAD; idx += 256) {
        int n = idx >> 5, dd = idx & 31;
        sv[n * 36 + dd] = g_v[base + idx];
    }
    if (tid < NTOK) {
        int wi = w & 63;
        int y = (wi >> 3) * WIN + tid / WIN;
        int x = (wi & 7)  * WIN + tid % WIN;
        int ry = (y < 49) ? 0 : ((y < 53) ? 1 : 2);
        int rx = (x < 49) ? 0 : ((x < 53) ? 1 : 2);
        sreg[tid] = ry * 3 + rx;
    }
    __syncthreads();

    const float scale = rsqrtf(g_sumq) * rsqrtf(g_sumk) / fmaxf(tau[0], 0.01f);

    // S = q k^T with 4x4 register tile
    {
        const int tj = tid & 15, ti = tid >> 4;
        float acc[4][4];
#pragma unroll
        for (int a = 0; a < 4; a++)
#pragma unroll
            for (int b = 0; b < 4; b++) acc[a][b] = 0.f;
#pragma unroll 8
        for (int kk = 0; kk < DHEAD; kk++) {
            float a0 = sq[(ti +  0) * 33 + kk];
            float a1 = sq[(ti + 16) * 33 + kk];
            float a2 = sq[(ti + 32) * 33 + kk];
            float a3 = sq[(ti + 48) * 33 + kk];
            float b0 = sk[(tj * 4 + 0) * 33 + kk];
            float b1 = sk[(tj * 4 + 1) * 33 + kk];
            float b2 = sk[(tj * 4 + 2) * 33 + kk];
            float b3 = sk[(tj * 4 + 3) * 33 + kk];
            acc[0][0] += a0 * b0; acc[0][1] += a0 * b1; acc[0][2] += a0 * b2; acc[0][3] += a0 * b3;
            acc[1][0] += a1 * b0; acc[1][1] += a1 * b1; acc[1][2] += a1 * b2; acc[1][3] += a1 * b3;
            acc[2][0] += a2 * b0; acc[2][1] += a2 * b1; acc[2][2] += a2 * b2; acc[2][3] += a2 * b3;
            acc[3][0] += a3 * b0; acc[3][1] += a3 * b1; acc[3][2] += a3 * b2; acc[3][3] += a3 * b3;
        }
        const float* bh = g_bias + hd * NTOK * NTOK;
#pragma unroll
        for (int a = 0; a < 4; a++) {
            int i = ti + 16 * a;
            if (i < NTOK) {
                int ri = sreg[i];
#pragma unroll
                for (int b = 0; b < 4; b++) {
                    int j = tj * 4 + b;
                    if (j < NTOK) {
                        float v = acc[a][b] * scale + bh[i * NTOK + j];
                        if (sreg[j] != ri) v -= 100.f;
                        ss[i * NTOK + j] = v;
                    }
                }
            }
        }
    }
    __syncthreads();

    // row softmax (one warp per row-set)
    {
        const int lane = tid & 31, wid = tid >> 5;
        for (int i = wid; i < NTOK; i += 8) {
            float v1 = (lane      < NTOK) ? ss[i * NTOK + lane]      : -1e30f;
            float v2 = (lane + 32 < NTOK) ? ss[i * NTOK + lane + 32] : -1e30f;
            float m = warp_max(fmaxf(v1, v2));
            float e1 = (lane      < NTOK) ? __expf(v1 - m) : 0.f;
            float e2 = (lane + 32 < NTOK) ? __expf(v2 - m) : 0.f;
            float s = warp_sum(e1 + e2);
            float inv = 1.f / s;
            if (lane      < NTOK) ss[i * NTOK + lane]      = e1 * inv;
            if (lane + 32 < NTOK) ss[i * NTOK + lane + 32] = e2 * inv;
        }
    }
    __syncthreads();

    // O = S v : thread = (row, 8 consecutive dd)
    {
        const int tc2 = tid & 3, tr2 = tid >> 2;   // tr2 in [0,64)
        if (tr2 < NTOK) {
            const int dd0 = tc2 * 8;
            float o0 = 0.f, o1 = 0.f, o2 = 0.f, o3 = 0.f;
            float o4 = 0.f, o5 = 0.f, o6 = 0.f, o7 = 0.f;
#pragma unroll 7
            for (int j = 0; j < NTOK; j++) {
                float p = ss[tr2 * NTOK + j];
                const float4 va = *reinterpret_cast<const float4*>(sv + j * 36 + dd0);
                const float4 vb = *reinterpret_cast<const float4*>(sv + j * 36 + dd0 + 4);
                o0 += p * va.x; o1 += p * va.y; o2 += p * va.z; o3 += p * va.w;
                o4 += p * vb.x; o5 += p * vb.y; o6 += p * vb.z; o7 += p * vb.w;
            }
            size_t ob = ((size_t)(w * NTOK + tr2)) * CCH + hd * DHEAD + dd0;
            *reinterpret_cast<float4*>(&g_o[ob])     = make_float4(o0, o1, o2, o3);
            *reinterpret_cast<float4*>(&g_o[ob + 4]) = make_float4(o4, o5, o6, o7);
        }
    }
}

// ---------------------------------------------------------------------------
// Launch
// ---------------------------------------------------------------------------
extern "C" void kernel_launch(void* const* d_in, const int* in_sizes, int n_in,
                              void* d_out, int out_size) {
    const float* x      = (const float*)d_in[0];
    const float* n1g    = (const float*)d_in[1];
    const float* n1b    = (const float*)d_in[2];
    const float* qkv_w  = (const float*)d_in[3];
    const float* qkv_b  = (const float*)d_in[4];
    const float* proj_w = (const float*)d_in[5];
    const float* proj_b = (const float*)d_in[6];
    const float* mw1    = (const float*)d_in[7];
    const float* mb1    = (const float*)d_in[8];
    const float* mw2    = (const float*)d_in[9];
    const float* mb2    = (const float*)d_in[10];
    const float* tau    = (const float*)d_in[11];
    const float* n2g    = (const float*)d_in[12];
    const float* n2b    = (const float*)d_in[13];
    const float* fc1w   = (const float*)d_in[14];
    const float* fc1b   = (const float*)d_in[15];
    const float* fc2w   = (const float*)d_in[16];
    const float* fc2b   = (const float*)d_in[17];
    float* out = (float*)d_out;

    prep_kernel<<<19, 128>>>(mw1, mb1, mw2, mb2);
    ln1_gather_kernel<<<TOKENS / 8, 256>>>(x, n1g, n1b);

    gemm_kernel<0><<<dim3(TOKENS / 64, 6), 256>>>(qkv_w, qkv_b, nullptr, nullptr);
    redsum_kernel<<<1024, 256>>>();
    redfinal_kernel<<<1, 256>>>();

    attn_kernel<<<NWTOT * NHEADS, 256>>>(tau);

    // x2 = x + window_reverse(o @ proj_w + proj_b)   (written to d_out)
    gemm_kernel<1><<<dim3(TOKENS / 64, 2), 256>>>(proj_w, proj_b, x, out);

    ln2_kernel<<<TOKENS / 8, 256>>>(out, n2g, n2b);
    gemm_kernel<2><<<dim3(TOKENS / 64, 8), 256>>>(fc1w, fc1b, nullptr, nullptr);
    gemm_kernel<3><<<dim3(TOKENS / 64, 2), 256>>>(fc2w, fc2b, nullptr, out);
}

// round 2
// speedup vs baseline: 1.8191x; 1.8191x over previous
#include <cuda_runtime.h>
#include <cstdint>

// ---------------------------------------------------------------------------
// Problem constants
// ---------------------------------------------------------------------------
#define BIMG   64
#define HWDIM  56
#define CCH    96
#define NHEADS 3
#define DHEAD  32
#define WIN    7
#define SHIFTW 3
#define NTOK   49                 // tokens per window
#define NWIN   64                 // windows per image (8x8)
#define NWTOT  (BIMG * NWIN)      // 4096 windows total
#define TOKENS (NWTOT * NTOK)     // 200704 tokens total
#define MLPH   384
#define METAH  128
#define LN_EPS 1e-5f

// ---------------------------------------------------------------------------
// Device scratch (static allocation: cudaMalloc is forbidden)
// ---------------------------------------------------------------------------
__device__ float g_h   [(size_t)TOKENS * CCH];       // LN1'd, shifted+windowed tokens
__device__ float g_q   [(size_t)NWTOT * NHEADS * NTOK * DHEAD];
__device__ float g_k   [(size_t)NWTOT * NHEADS * NTOK * DHEAD];
__device__ float g_v   [(size_t)NWTOT * NHEADS * NTOK * DHEAD];
__device__ float g_o   [(size_t)TOKENS * CCH];       // attention output (window layout)
__device__ float g_ln2 [(size_t)TOKENS * CCH];       // LN2(x2)
__device__ float g_hid [(size_t)TOKENS * MLPH];      // gelu(fc1)
__device__ float g_bias[NHEADS * NTOK * NTOK];       // log-CPB bias table
__device__ float g_pq[1024], g_pk[1024];             // partial sums (deterministic)
__device__ float g_sumq, g_sumk;

// ---------------------------------------------------------------------------
// Helpers
// ---------------------------------------------------------------------------
__device__ __forceinline__ float warp_sum(float v) {
#pragma unroll
    for (int o = 16; o; o >>= 1) v += __shfl_xor_sync(0xffffffffu, v, o);
    return v;
}
__device__ __forceinline__ float warp_max(float v) {
#pragma unroll
    for (int o = 16; o; o >>= 1) v = fmaxf(v, __shfl_xor_sync(0xffffffffu, v, o));
    return v;
}
__device__ __forceinline__ float gelu_tanh(float x) {
    float x3 = x * x * x;
    return 0.5f * x * (1.f + tanhf(0.7978845608028654f * (x + 0.044715f * x3)));
}
__device__ __forceinline__ uint32_t to_tf32(float f) {
    uint32_t u;
    asm("cvt.rna.tf32.f32 %0, %1;" : "=r"(u) : "f"(f));
    return u;
}
__device__ __forceinline__ void mma_tf32(float c[4], const uint32_t a[4], const uint32_t b[2]) {
    asm volatile(
        "mma.sync.aligned.m16n8k8.row.col.f32.tf32.tf32.f32 "
        "{%0,%1,%2,%3}, {%4,%5,%6,%7}, {%8,%9}, {%0,%1,%2,%3};"
        : "+f"(c[0]), "+f"(c[1]), "+f"(c[2]), "+f"(c[3])
        : "r"(a[0]), "r"(a[1]), "r"(a[2]), "r"(a[3]), "r"(b[0]), "r"(b[1]));
}

// ---------------------------------------------------------------------------
// Prep: log-CPB bias table (3 x 49 x 49) from the meta-MLP. 2401 threads.
// ---------------------------------------------------------------------------
__global__ void prep_kernel(const float* __restrict__ w1, const float* __restrict__ b1,
                            const float* __restrict__ w2, const float* __restrict__ b2) {
    int idx = blockIdx.x * blockDim.x + threadIdx.x;
    if (idx >= NTOK * NTOK) return;
    int i = idx / NTOK, j = idx % NTOK;
    float d0 = (float)(i / WIN - j / WIN);
    float d1 = (float)(i % WIN - j % WIN);
    float r0 = copysignf(log1pf(fabsf(d0)), d0);
    float r1 = copysignf(log1pf(fabsf(d1)), d1);
    float a0 = 0.f, a1 = 0.f, a2 = 0.f;
#pragma unroll 4
    for (int m = 0; m < METAH; m++) {
        float hsum = r0 * w1[m] + r1 * w1[METAH + m] + b1[m];
        float gl = gelu_tanh(hsum);
        a0 += gl * w2[m * 3 + 0];
        a1 += gl * w2[m * 3 + 1];
        a2 += gl * w2[m * 3 + 2];
    }
    g_bias[0 * NTOK * NTOK + idx] = a0 + b2[0];
    g_bias[1 * NTOK * NTOK + idx] = a1 + b2[1];
    g_bias[2 * NTOK * NTOK + idx] = a2 + b2[2];
}

// ---------------------------------------------------------------------------
// LN1 + cyclic shift + window partition.  One warp per token.
// ---------------------------------------------------------------------------
__global__ __launch_bounds__(256) void ln1_gather_kernel(const float* __restrict__ x,
                                                         const float* __restrict__ g,
                                                         const float* __restrict__ b) {
    int warp = (blockIdx.x * blockDim.x + threadIdx.x) >> 5;
    int lane = threadIdx.x & 31;
    if (warp >= TOKENS) return;
    int w = warp / NTOK, n = warp % NTOK;
    int bimg = w >> 6, wi = w & 63;
    int Y = (wi >> 3) * WIN + n / WIN + SHIFTW; if (Y >= HWDIM) Y -= HWDIM;
    int X = (wi & 7)  * WIN + n % WIN + SHIFTW; if (X >= HWDIM) X -= HWDIM;
    const float* src = x + ((size_t)bimg * (HWDIM * HWDIM) + Y * HWDIM + X) * CCH;
    float v0 = src[lane], v1 = src[lane + 32], v2 = src[lane + 64];
    float s  = warp_sum(v0 + v1 + v2);
    float sq = warp_sum(v0 * v0 + v1 * v1 + v2 * v2);
    float mean = s * (1.f / CCH);
    float var  = sq * (1.f / CCH) - mean * mean;
    float inv  = rsqrtf(var + LN_EPS);
    float* dst = g_h + (size_t)warp * CCH;
    dst[lane]      = (v0 - mean) * inv * g[lane]      + b[lane];
    dst[lane + 32] = (v1 - mean) * inv * g[lane + 32] + b[lane + 32];
    dst[lane + 64] = (v2 - mean) * inv * g[lane + 64] + b[lane + 64];
}

// ---------------------------------------------------------------------------
// LN2 over x2 (= d_out after proj kernel), linear token layout.
// ---------------------------------------------------------------------------
__global__ __launch_bounds__(256) void ln2_kernel(const float* __restrict__ x2,
                                                  const float* __restrict__ g,
                                                  const float* __restrict__ b) {
    int warp = (blockIdx.x * blockDim.x + threadIdx.x) >> 5;
    int lane = threadIdx.x & 31;
    if (warp >= TOKENS) return;
    const float* src = x2 + (size_t)warp * CCH;
    float v0 = src[lane], v1 = src[lane + 32], v2 = src[lane + 64];
    float s  = warp_sum(v0 + v1 + v2);
    float sq = warp_sum(v0 * v0 + v1 * v1 + v2 * v2);
    float mean = s * (1.f / CCH);
    float var  = sq * (1.f / CCH) - mean * mean;
    float inv  = rsqrtf(var + LN_EPS);
    float* dst = g_ln2 + (size_t)warp * CCH;
    dst[lane]      = (v0 - mean) * inv * g[lane]      + b[lane];
    dst[lane + 32] = (v1 - mean) * inv * g[lane + 32] + b[lane + 32];
    dst[lane + 64] = (v2 - mean) * inv * g[lane + 64] + b[lane + 64];
}

// ---------------------------------------------------------------------------
// Per-element GEMM epilogues
// EPI 0: qkv  scatter into g_q/g_k/g_v (+qkv_b)
// EPI 1: proj -> d_out = x + window_reverse(proj)
// EPI 2: fc1  -> g_hid = gelu(.)
// EPI 3: fc2  -> d_out += .
// ---------------------------------------------------------------------------
template <int EPI>
__device__ __forceinline__ void epilogue(int row, int col, float val,
                                         const float* __restrict__ bias,
                                         const float* __restrict__ Xres,
                                         float* __restrict__ out) {
    if (EPI == 0) {
        val += bias[col];
        int s  = col / 96;
        int hd = (col % 96) / DHEAD;
        int dd = col & (DHEAD - 1);
        int w  = row / NTOK, n = row % NTOK;
        size_t oi = ((size_t)(w * NHEADS + hd) * NTOK + n) * DHEAD + dd;
        float* dst = (s == 0) ? g_q : (s == 1) ? g_k : g_v;
        dst[oi] = val;
    } else if (EPI == 1) {
        val += bias[col];
        int w = row / NTOK, n = row % NTOK;
        int b = w >> 6, wi = w & 63;
        int Y = (wi >> 3) * WIN + n / WIN + SHIFTW; if (Y >= HWDIM) Y -= HWDIM;
        int X = (wi & 7)  * WIN + n % WIN + SHIFTW; if (X >= HWDIM) X -= HWDIM;
        size_t oi = ((size_t)b * (HWDIM * HWDIM) + Y * HWDIM + X) * CCH + col;
        out[oi] = Xres[oi] + val;
    } else if (EPI == 2) {
        g_hid[(size_t)row * MLPH + col] = gelu_tanh(val + bias[col]);
    } else {
        out[(size_t)row * CCH + col] += val + bias[col];
    }
}

// ---------------------------------------------------------------------------
// tf32 tensor-core GEMM. BM=128, BN=48, BK=32, 256 threads (8 warps, 4x2),
// warp tile 32x24 = 2x3 m16n8k8 mma tiles.  A row-major, B (weights) row-major
// consumed as col-major fragments.  grid = (N/48, M/128) so consecutive blocks
// share the same A M-tile (L2 reuse); weights are tiny and L2-resident.
// ---------------------------------------------------------------------------
template <int EPI>
__global__ __launch_bounds__(256) void mma_gemm_kernel(const float* __restrict__ Bw,
                                                       const float* __restrict__ bias,
                                                       const float* __restrict__ Xres,
                                                       float* __restrict__ out) {
    constexpr int N   = (EPI == 0) ? 288 : (EPI == 2) ? 384 : 96;
    constexpr int KT  = (EPI == 3) ? 384 : 96;
    constexpr int NCH = KT / 32;
    const float* __restrict__ A =
        (EPI == 0) ? g_h : (EPI == 1) ? g_o : (EPI == 2) ? g_ln2 : g_hid;

    __shared__ float sA[128 * 36];   // stride 36: a-frag banks (4r+c)%32 distinct
    __shared__ float sB[32 * 56];    // stride 56: b-frag banks (24k+n)%32 distinct

    const int tid  = threadIdx.x;
    const int lane = tid & 31;
    const int wid  = tid >> 5;
    const int wr   = wid >> 1;       // warp row 0..3
    const int wc   = wid & 1;        // warp col 0..1
    const int n0   = blockIdx.x * 48;
    const int m0   = blockIdx.y * 128;

    float acc[2][3][4];
#pragma unroll
    for (int mi = 0; mi < 2; mi++)
#pragma unroll
        for (int ni = 0; ni < 3; ni++)
#pragma unroll
            for (int e = 0; e < 4; e++) acc[mi][ni][e] = 0.f;

    for (int kc = 0; kc < NCH; kc++) {
        // load A chunk 128x32 (float4, cvt to tf32 bits)
#pragma unroll
        for (int l = 0; l < 4; l++) {
            int idx = tid + l * 256;            // 0..1023 over 128*8 float4
            int r = idx >> 3, c4 = idx & 7;
            const float4 v = *reinterpret_cast<const float4*>(
                &A[(size_t)(m0 + r) * KT + kc * 32 + c4 * 4]);
            float* d = &sA[r * 36 + c4 * 4];
            d[0] = __uint_as_float(to_tf32(v.x));
            d[1] = __uint_as_float(to_tf32(v.y));
            d[2] = __uint_as_float(to_tf32(v.z));
            d[3] = __uint_as_float(to_tf32(v.w));
        }
        // load B chunk 32x48
#pragma unroll
        for (int l = 0; l < 2; l++) {
            int idx = tid + l * 256;            // need < 384 (32*12 float4)
            if (idx < 384) {
                int k = idx / 12, c4 = idx % 12;
                const float4 v = *reinterpret_cast<const float4*>(
                    &Bw[(size_t)(kc * 32 + k) * N + n0 + c4 * 4]);
                float* d = &sB[k * 56 + c4 * 4];
                d[0] = __uint_as_float(to_tf32(v.x));
                d[1] = __uint_as_float(to_tf32(v.y));
                d[2] = __uint_as_float(to_tf32(v.z));
                d[3] = __uint_as_float(to_tf32(v.w));
            }
        }
        __syncthreads();

#pragma unroll
        for (int k8 = 0; k8 < 4; k8++) {
            const int kb = k8 * 8;
            uint32_t af[2][4], bf[3][2];
#pragma unroll
            for (int mi = 0; mi < 2; mi++) {
                int rb = wr * 32 + mi * 16 + (lane >> 2);
                int cc = kb + (lane & 3);
                af[mi][0] = __float_as_uint(sA[rb * 36 + cc]);
                af[mi][1] = __float_as_uint(sA[(rb + 8) * 36 + cc]);
                af[mi][2] = __float_as_uint(sA[rb * 36 + cc + 4]);
                af[mi][3] = __float_as_uint(sA[(rb + 8) * 36 + cc + 4]);
            }
#pragma unroll
            for (int ni = 0; ni < 3; ni++) {
                int cb = wc * 24 + ni * 8 + (lane >> 2);
                int kk = kb + (lane & 3);
                bf[ni][0] = __float_as_uint(sB[kk * 56 + cb]);
                bf[ni][1] = __float_as_uint(sB[(kk + 4) * 56 + cb]);
            }
#pragma unroll
            for (int mi = 0; mi < 2; mi++)
#pragma unroll
                for (int ni = 0; ni < 3; ni++)
                    mma_tf32(acc[mi][ni], af[mi], bf[ni]);
        }
        __syncthreads();
    }

    // epilogue: c0=(r, 2c) c1=(r, 2c+1) c2=(r+8, 2c) c3=(r+8, 2c+1)
#pragma unroll
    for (int mi = 0; mi < 2; mi++)
#pragma unroll
        for (int ni = 0; ni < 3; ni++) {
            int r = m0 + wr * 32 + mi * 16 + (lane >> 2);
            int c = n0 + wc * 24 + ni * 8 + 2 * (lane & 3);
            epilogue<EPI>(r,     c,     acc[mi][ni][0], bias, Xres, out);
            epilogue<EPI>(r,     c + 1, acc[mi][ni][1], bias, Xres, out);
            epilogue<EPI>(r + 8, c,     acc[mi][ni][2], bias, Xres, out);
            epilogue<EPI>(r + 8, c + 1, acc[mi][ni][3], bias, Xres, out);
        }
}

// ---------------------------------------------------------------------------
// Deterministic global sum-of-squares of q and k (two stages, no atomics)
// ---------------------------------------------------------------------------
__global__ __launch_bounds__(256) void redsum_kernel() {
    const size_t n = (size_t)TOKENS * CCH;
    float lq = 0.f, lk = 0.f;
    for (size_t i = (size_t)blockIdx.x * 256 + threadIdx.x; i < n; i += (size_t)1024 * 256) {
        float a = g_q[i]; lq += a * a;
        float b = g_k[i]; lk += b * b;
    }
    lq = warp_sum(lq); lk = warp_sum(lk);
    __shared__ float sq8[8], sk8[8];
    if ((threadIdx.x & 31) == 0) { sq8[threadIdx.x >> 5] = lq; sk8[threadIdx.x >> 5] = lk; }
    __syncthreads();
    if (threadIdx.x == 0) {
        float a = 0.f, b = 0.f;
#pragma unroll
        for (int i = 0; i < 8; i++) { a += sq8[i]; b += sk8[i]; }
        g_pq[blockIdx.x] = a; g_pk[blockIdx.x] = b;
    }
}
__global__ __launch_bounds__(256) void redfinal_kernel() {
    float lq = 0.f, lk = 0.f;
    for (int i = threadIdx.x; i < 1024; i += 256) { lq += g_pq[i]; lk += g_pk[i]; }
    lq = warp_sum(lq); lk = warp_sum(lk);
    __shared__ float sq8[8], sk8[8];
    if ((threadIdx.x & 31) == 0) { sq8[threadIdx.x >> 5] = lq; sk8[threadIdx.x >> 5] = lk; }
    __syncthreads();
    if (threadIdx.x == 0) {
        float a = 0.f, b = 0.f;
#pragma unroll
        for (int i = 0; i < 8; i++) { a += sq8[i]; b += sk8[i]; }
        g_sumq = a; g_sumk = b;
    }
}

// ---------------------------------------------------------------------------
// Attention: one block per (window, head).
// ---------------------------------------------------------------------------
__global__ __launch_bounds__(256) void attn_kernel(const float* __restrict__ tau) {
    __shared__ float sq[64 * 33];
    __shared__ float sk[64 * 33];
    __shared__ float sv[49 * 36];
    __shared__ float ss[49 * 49];
    __shared__ int   sreg[49];

    const int blk = blockIdx.x;
    const int w = blk / NHEADS, hd = blk % NHEADS;
    const int tid = threadIdx.x;
    const size_t base = (size_t)(w * NHEADS + hd) * NTOK * DHEAD;

    for (int idx = tid; idx < 64 * DHEAD; idx += 256) {
        int n = idx >> 5, dd = idx & 31;
        float qv = 0.f, kv = 0.f;
        if (n < NTOK) { qv = g_q[base + idx]; kv = g_k[base + idx]; }
        sq[n * 33 + dd] = qv;
        sk[n * 33 + dd] = kv;
    }
    for (int idx = tid; idx < NTOK * DHEAD; idx += 256) {
        int n = idx >> 5, dd = idx & 31;
        sv[n * 36 + dd] = g_v[base + idx];
    }
    if (tid < NTOK) {
        int wi = w & 63;
        int y = (wi >> 3) * WIN + tid / WIN;
        int x = (wi & 7)  * WIN + tid % WIN;
        int ry = (y < 49) ? 0 : ((y < 53) ? 1 : 2);
        int rx = (x < 49) ? 0 : ((x < 53) ? 1 : 2);
        sreg[tid] = ry * 3 + rx;
    }
    __syncthreads();

    const float scale = rsqrtf(g_sumq) * rsqrtf(g_sumk) / fmaxf(tau[0], 0.01f);

    {
        const int tj = tid & 15, ti = tid >> 4;
        float acc[4][4];
#pragma unroll
        for (int a = 0; a < 4; a++)
#pragma unroll
            for (int b = 0; b < 4; b++) acc[a][b] = 0.f;
#pragma unroll 8
        for (int kk = 0; kk < DHEAD; kk++) {
            float a0 = sq[(ti +  0) * 33 + kk];
            float a1 = sq[(ti + 16) * 33 + kk];
            float a2 = sq[(ti + 32) * 33 + kk];
            float a3 = sq[(ti + 48) * 33 + kk];
            float b0 = sk[(tj * 4 + 0) * 33 + kk];
            float b1 = sk[(tj * 4 + 1) * 33 + kk];
            float b2 = sk[(tj * 4 + 2) * 33 + kk];
            float b3 = sk[(tj * 4 + 3) * 33 + kk];
            acc[0][0] += a0 * b0; acc[0][1] += a0 * b1; acc[0][2] += a0 * b2; acc[0][3] += a0 * b3;
            acc[1][0] += a1 * b0; acc[1][1] += a1 * b1; acc[1][2] += a1 * b2; acc[1][3] += a1 * b3;
            acc[2][0] += a2 * b0; acc[2][1] += a2 * b1; acc[2][2] += a2 * b2; acc[2][3] += a2 * b3;
            acc[3][0] += a3 * b0; acc[3][1] += a3 * b1; acc[3][2] += a3 * b2; acc[3][3] += a3 * b3;
        }
        const float* bh = g_bias + hd * NTOK * NTOK;
#pragma unroll
        for (int a = 0; a < 4; a++) {
            int i = ti + 16 * a;
            if (i < NTOK) {
                int ri = sreg[i];
#pragma unroll
                for (int b = 0; b < 4; b++) {
                    int j = tj * 4 + b;
                    if (j < NTOK) {
                        float v = acc[a][b] * scale + bh[i * NTOK + j];
                        if (sreg[j] != ri) v -= 100.f;
                        ss[i * NTOK + j] = v;
                    }
                }
            }
        }
    }
    __syncthreads();

    {
        const int lane = tid & 31, wd = tid >> 5;
        for (int i = wd; i < NTOK; i += 8) {
            float v1 = (lane      < NTOK) ? ss[i * NTOK + lane]      : -1e30f;
            float v2 = (lane + 32 < NTOK) ? ss[i * NTOK + lane + 32] : -1e30f;
            float m = warp_max(fmaxf(v1, v2));
            float e1 = (lane      < NTOK) ? __expf(v1 - m) : 0.f;
            float e2 = (lane + 32 < NTOK) ? __expf(v2 - m) : 0.f;
            float s = warp_sum(e1 + e2);
            float inv = 1.f / s;
            if (lane      < NTOK) ss[i * NTOK + lane]      = e1 * inv;
            if (lane + 32 < NTOK) ss[i * NTOK + lane + 32] = e2 * inv;
        }
    }
    __syncthreads();

    {
        const int tc2 = tid & 3, tr2 = tid >> 2;
        if (tr2 < NTOK) {
            const int dd0 = tc2 * 8;
            float o0 = 0.f, o1 = 0.f, o2 = 0.f, o3 = 0.f;
            float o4 = 0.f, o5 = 0.f, o6 = 0.f, o7 = 0.f;
#pragma unroll 7
            for (int j = 0; j < NTOK; j++) {
                float p = ss[tr2 * NTOK + j];
                const float4 va = *reinterpret_cast<const float4*>(sv + j * 36 + dd0);
                const float4 vb = *reinterpret_cast<const float4*>(sv + j * 36 + dd0 + 4);
                o0 += p * va.x; o1 += p * va.y; o2 += p * va.z; o3 += p * va.w;
                o4 += p * vb.x; o5 += p * vb.y; o6 += p * vb.z; o7 += p * vb.w;
            }
            size_t ob = ((size_t)(w * NTOK + tr2)) * CCH + hd * DHEAD + dd0;
            *reinterpret_cast<float4*>(&g_o[ob])     = make_float4(o0, o1, o2, o3);
            *reinterpret_cast<float4*>(&g_o[ob + 4]) = make_float4(o4, o5, o6, o7);
        }
    }
}

// ---------------------------------------------------------------------------
// Launch
// ---------------------------------------------------------------------------
extern "C" void kernel_launch(void* const* d_in, const int* in_sizes, int n_in,
                              void* d_out, int out_size) {
    const float* x      = (const float*)d_in[0];
    const float* n1g    = (const float*)d_in[1];
    const float* n1b    = (const float*)d_in[2];
    const float* qkv_w  = (const float*)d_in[3];
    const float* qkv_b  = (const float*)d_in[4];
    const float* proj_w = (const float*)d_in[5];
    const float* proj_b = (const float*)d_in[6];
    const float* mw1    = (const float*)d_in[7];
    const float* mb1    = (const float*)d_in[8];
    const float* mw2    = (const float*)d_in[9];
    const float* mb2    = (const float*)d_in[10];
    const float* tau    = (const float*)d_in[11];
    const float* n2g    = (const float*)d_in[12];
    const float* n2b    = (const float*)d_in[13];
    const float* fc1w   = (const float*)d_in[14];
    const float* fc1b   = (const float*)d_in[15];
    const float* fc2w   = (const float*)d_in[16];
    const float* fc2b   = (const float*)d_in[17];
    float* out = (float*)d_out;

    prep_kernel<<<19, 128>>>(mw1, mb1, mw2, mb2);
    ln1_gather_kernel<<<TOKENS / 8, 256>>>(x, n1g, n1b);

    mma_gemm_kernel<0><<<dim3(6, TOKENS / 128), 256>>>(qkv_w, qkv_b, nullptr, nullptr);
    redsum_kernel<<<1024, 256>>>();
    redfinal_kernel<<<1, 256>>>();

    attn_kernel<<<NWTOT * NHEADS, 256>>>(tau);

    // x2 = x + window_reverse(o @ proj_w + proj_b)   (written to d_out)
    mma_gemm_kernel<1><<<dim3(2, TOKENS / 128), 256>>>(proj_w, proj_b, x, out);

    ln2_kernel<<<TOKENS / 8, 256>>>(out, n2g, n2b);
    mma_gemm_kernel<2><<<dim3(8, TOKENS / 128), 256>>>(fc1w, fc1b, nullptr, nullptr);
    mma_gemm_kernel<3><<<dim3(2, TOKENS / 128), 256>>>(fc2w, fc2b, nullptr, out);
}

// round 5
// speedup vs baseline: 2.7806x; 1.5286x over previous
#include <cuda_runtime.h>
#include <cuda_fp16.h>
#include <cstdint>

// ---------------------------------------------------------------------------
// Problem constants
// ---------------------------------------------------------------------------
#define BIMG   64
#define HWDIM  56
#define CCH    96
#define NHEADS 3
#define DHEAD  32
#define WIN    7
#define SHIFTW 3
#define NTOK   49
#define NWIN   64
#define NWTOT  (BIMG * NWIN)      // 4096
#define TOKENS (NWTOT * NTOK)     // 200704
#define MLPH   384
#define METAH  128
#define LN_EPS 1e-5f

// ---------------------------------------------------------------------------
// Device scratch (static; cudaMalloc forbidden)
// ---------------------------------------------------------------------------
__device__ __align__(16) __half g_h_h  [(size_t)TOKENS * CCH];
__device__ __align__(16) __half g_q_h  [(size_t)TOKENS * CCH];
__device__ __align__(16) __half g_k_h  [(size_t)TOKENS * CCH];
__device__ __align__(16) __half g_v_h  [(size_t)TOKENS * CCH];
__device__ __align__(16) __half g_o_h  [(size_t)TOKENS * CCH];
__device__ __align__(16) __half g_ln2_h[(size_t)TOKENS * CCH];
__device__ __align__(16) __half g_hid_h[(size_t)TOKENS * MLPH];
__device__ __align__(16) __half g_wqkv [96 * 288];
__device__ __align__(16) __half g_wproj[96 * 96];
__device__ __align__(16) __half g_wfc1 [96 * 384];
__device__ __align__(16) __half g_wfc2 [384 * 96];
__device__ float g_bias[NHEADS * NTOK * NTOK];
__device__ float g_pq[3136], g_pk[3136];
__device__ float g_sumq, g_sumk;

// ---------------------------------------------------------------------------
// Helpers
// ---------------------------------------------------------------------------
__device__ __forceinline__ float warp_sum(float v) {
#pragma unroll
    for (int o = 16; o; o >>= 1) v += __shfl_xor_sync(0xffffffffu, v, o);
    return v;
}
__device__ __forceinline__ float warp_max(float v) {
#pragma unroll
    for (int o = 16; o; o >>= 1) v = fmaxf(v, __shfl_xor_sync(0xffffffffu, v, o));
    return v;
}
__device__ __forceinline__ float gelu_tanh(float x) {
    float x3 = x * x * x;
    return 0.5f * x * (1.f + tanhf(0.7978845608028654f * (x + 0.044715f * x3)));
}
__device__ __forceinline__ uint32_t smem_u32(const void* p) {
    return (uint32_t)__cvta_generic_to_shared(p);
}
__device__ __forceinline__ void cp16(uint32_t dst, const void* src) {
    asm volatile("cp.async.cg.shared.global [%0], [%1], 16;" :: "r"(dst), "l"(src));
}
__device__ __forceinline__ void ldsm4(uint32_t& r0, uint32_t& r1, uint32_t& r2, uint32_t& r3, uint32_t a) {
    asm volatile("ldmatrix.sync.aligned.m8n8.x4.shared.b16 {%0,%1,%2,%3}, [%4];"
                 : "=r"(r0), "=r"(r1), "=r"(r2), "=r"(r3) : "r"(a));
}
__device__ __forceinline__ void ldsm4t(uint32_t& r0, uint32_t& r1, uint32_t& r2, uint32_t& r3, uint32_t a) {
    asm volatile("ldmatrix.sync.aligned.m8n8.x4.trans.shared.b16 {%0,%1,%2,%3}, [%4];"
                 : "=r"(r0), "=r"(r1), "=r"(r2), "=r"(r3) : "r"(a));
}
__device__ __forceinline__ void ldsm2t(uint32_t& r0, uint32_t& r1, uint32_t a) {
    asm volatile("ldmatrix.sync.aligned.m8n8.x2.trans.shared.b16 {%0,%1}, [%2];"
                 : "=r"(r0), "=r"(r1) : "r"(a));
}
__device__ __forceinline__ void mma_f16(float c[4], const uint32_t a[4], const uint32_t b[2]) {
    asm volatile(
        "mma.sync.aligned.m16n8k16.row.col.f32.f16.f16.f32 "
        "{%0,%1,%2,%3}, {%4,%5,%6,%7}, {%8,%9}, {%0,%1,%2,%3};"
        : "+f"(c[0]), "+f"(c[1]), "+f"(c[2]), "+f"(c[3])
        : "r"(a[0]), "r"(a[1]), "r"(a[2]), "r"(a[3]), "r"(b[0]), "r"(b[1]));
}
// pack two floats -> one u32 of two fp16, intrinsics only (no address-of-local)
__device__ __forceinline__ uint32_t pack_h2(float lo, float hi) {
    __half2 h = __floats2half2_rn(lo, hi);
    return (uint32_t)__half_as_ushort(__low2half(h)) |
           ((uint32_t)__half_as_ushort(__high2half(h)) << 16);
}

// ---------------------------------------------------------------------------
// Weight fp32 -> fp16 conversion (device code writing device symbols: legal)
// ---------------------------------------------------------------------------
__global__ void convw_kernel(const float* __restrict__ qkvw, const float* __restrict__ projw,
                             const float* __restrict__ fc1w, const float* __restrict__ fc2w) {
    int i = blockIdx.x * blockDim.x + threadIdx.x;
    if (i < 27648)            g_wqkv[i]          = __float2half_rn(qkvw[i]);
    else if (i < 36864)       g_wproj[i - 27648] = __float2half_rn(projw[i - 27648]);
    else if (i < 73728)       g_wfc1[i - 36864]  = __float2half_rn(fc1w[i - 36864]);
    else if (i < 110592)      g_wfc2[i - 73728]  = __float2half_rn(fc2w[i - 73728]);
}

// ---------------------------------------------------------------------------
// Prep: log-CPB bias table (3 x 49 x 49)
// ---------------------------------------------------------------------------
__global__ void prep_kernel(const float* __restrict__ w1, const float* __restrict__ b1,
                            const float* __restrict__ w2, const float* __restrict__ b2) {
    int idx = blockIdx.x * blockDim.x + threadIdx.x;
    if (idx >= NTOK * NTOK) return;
    int i = idx / NTOK, j = idx % NTOK;
    float d0 = (float)(i / WIN - j / WIN);
    float d1 = (float)(i % WIN - j % WIN);
    float r0 = copysignf(log1pf(fabsf(d0)), d0);
    float r1 = copysignf(log1pf(fabsf(d1)), d1);
    float a0 = 0.f, a1 = 0.f, a2 = 0.f;
#pragma unroll 4
    for (int m = 0; m < METAH; m++) {
        float hsum = r0 * w1[m] + r1 * w1[METAH + m] + b1[m];
        float gl = gelu_tanh(hsum);
        a0 += gl * w2[m * 3 + 0];
        a1 += gl * w2[m * 3 + 1];
        a2 += gl * w2[m * 3 + 2];
    }
    g_bias[0 * NTOK * NTOK + idx] = a0 + b2[0];
    g_bias[1 * NTOK * NTOK + idx] = a1 + b2[1];
    g_bias[2 * NTOK * NTOK + idx] = a2 + b2[2];
}

// ---------------------------------------------------------------------------
// LN1 + cyclic shift + window partition -> g_h_h (fp16). One warp per token.
// ---------------------------------------------------------------------------
__global__ __launch_bounds__(256) void ln1_gather_kernel(const float* __restrict__ x,
                                                         const float* __restrict__ g,
                                                         const float* __restrict__ b) {
    int warp = (blockIdx.x * blockDim.x + threadIdx.x) >> 5;
    int lane = threadIdx.x & 31;
    if (warp >= TOKENS) return;
    int w = warp / NTOK, n = warp % NTOK;
    int bimg = w >> 6, wi = w & 63;
    int Y = (wi >> 3) * WIN + n / WIN + SHIFTW; if (Y >= HWDIM) Y -= HWDIM;
    int X = (wi & 7)  * WIN + n % WIN + SHIFTW; if (X >= HWDIM) X -= HWDIM;
    const float* src = x + ((size_t)bimg * (HWDIM * HWDIM) + Y * HWDIM + X) * CCH;
    float v0 = src[lane], v1 = src[lane + 32], v2 = src[lane + 64];
    float s  = warp_sum(v0 + v1 + v2);
    float sq = warp_sum(v0 * v0 + v1 * v1 + v2 * v2);
    float mean = s * (1.f / CCH);
    float var  = sq * (1.f / CCH) - mean * mean;
    float inv  = rsqrtf(var + LN_EPS);
    __half* dst = g_h_h + (size_t)warp * CCH;
    dst[lane]      = __float2half_rn((v0 - mean) * inv * g[lane]      + b[lane]);
    dst[lane + 32] = __float2half_rn((v1 - mean) * inv * g[lane + 32] + b[lane + 32]);
    dst[lane + 64] = __float2half_rn((v2 - mean) * inv * g[lane + 64] + b[lane + 64]);
}

// ---------------------------------------------------------------------------
// LN2 over x2 (= d_out) -> g_ln2_h (fp16)
// ---------------------------------------------------------------------------
__global__ __launch_bounds__(256) void ln2_kernel(const float* __restrict__ x2,
                                                  const float* __restrict__ g,
                                                  const float* __restrict__ b) {
    int warp = (blockIdx.x * blockDim.x + threadIdx.x) >> 5;
    int lane = threadIdx.x & 31;
    if (warp >= TOKENS) return;
    const float* src = x2 + (size_t)warp * CCH;
    float v0 = src[lane], v1 = src[lane + 32], v2 = src[lane + 64];
    float s  = warp_sum(v0 + v1 + v2);
    float sq = warp_sum(v0 * v0 + v1 * v1 + v2 * v2);
    float mean = s * (1.f / CCH);
    float var  = sq * (1.f / CCH) - mean * mean;
    float inv  = rsqrtf(var + LN_EPS);
    __half* dst = g_ln2_h + (size_t)warp * CCH;
    dst[lane]      = __float2half_rn((v0 - mean) * inv * g[lane]      + b[lane]);
    dst[lane + 32] = __float2half_rn((v1 - mean) * inv * g[lane + 32] + b[lane + 32]);
    dst[lane + 64] = __float2half_rn((v2 - mean) * inv * g[lane + 64] + b[lane + 64]);
}

// ---------------------------------------------------------------------------
// GEMM stage loader (plain function: no lambda, no captured state)
// ---------------------------------------------------------------------------
template <int N, int KT>
__device__ __forceinline__ void gemm_load_stage(const __half* __restrict__ A,
                                                const __half* __restrict__ Bw,
                                                int m0, int n0, int kc,
                                                __half* sAst, __half* sBst, int tid) {
#pragma unroll
    for (int i = 0; i < 3; i++) {
        int idx = tid + i * 256;
        int r = idx / 6, c = idx - r * 6;
        const __half* src = A + (size_t)(m0 + r) * KT + kc * 48 + c * 8;
        cp16(smem_u32(sAst + r * 64 + ((c ^ (r & 7)) * 8)), src);
    }
#pragma unroll
    for (int i = 0; i < 2; i++) {
        int idx = tid + i * 256;
        if (idx < 288) {
            int r = idx / 6, c = idx - r * 6;
            const __half* src = Bw + (size_t)(kc * 48 + r) * N + n0 + c * 8;
            cp16(smem_u32(sBst + r * 64 + ((c ^ (r & 7)) * 8)), src);
        }
    }
    asm volatile("cp.async.commit_group;");
}

// ---------------------------------------------------------------------------
// fp16 tensor-core GEMM. BM=128, BN=48, BK=48, 2-stage cp.async pipeline,
// 8 warps (4m x 2n), warp tile 32x24 (2x3 m16n8k16), ldmatrix fragments.
// A and W selected IN-KERNEL from device symbols (never passed from host).
// EPI 0: qkv -> g_q/g_k/g_v (fp16) + fused per-block sum(q^2), sum(k^2)
// EPI 1: proj -> d_out = x + window_reverse(proj)          (fp32)
// EPI 2: fc1 -> g_hid = gelu(.)                            (fp16)
// EPI 3: fc2 -> d_out += .                                 (fp32)
// ---------------------------------------------------------------------------
template <int EPI>
__global__ __launch_bounds__(256) void hgemm_kernel(const float* __restrict__ bias,
                                                    const float* __restrict__ Xres,
                                                    float* __restrict__ out) {
    constexpr int N   = (EPI == 0) ? 288 : (EPI == 2) ? 384 : 96;
    constexpr int KT  = (EPI == 3) ? 384 : 96;
    constexpr int NCH = KT / 48;
    const __half* __restrict__ A =
        (EPI == 0) ? g_h_h : (EPI == 1) ? g_o_h : (EPI == 2) ? g_ln2_h : g_hid_h;
    const __half* __restrict__ Bw =
        (EPI == 0) ? g_wqkv : (EPI == 1) ? g_wproj : (EPI == 2) ? g_wfc1 : g_wfc2;

    __shared__ __align__(16) __half sA[2][128 * 64];
    __shared__ __align__(16) __half sB[2][48 * 64];
    __shared__ float red[8];

    const int tid  = threadIdx.x;
    const int lane = tid & 31;
    const int wid  = tid >> 5;
    const int wr   = wid >> 1;
    const int wc   = wid & 1;
    const int n0   = blockIdx.x * 48;
    const int m0   = blockIdx.y * 128;

    float acc[2][3][4];
#pragma unroll
    for (int mi = 0; mi < 2; mi++)
#pragma unroll
        for (int ni = 0; ni < 3; ni++)
#pragma unroll
            for (int e = 0; e < 4; e++) acc[mi][ni][e] = 0.f;

    gemm_load_stage<N, KT>(A, Bw, m0, n0, 0, sA[0], sB[0], tid);

#pragma unroll 1
    for (int kc = 0; kc < NCH; kc++) {
        if (kc + 1 < NCH) {
            gemm_load_stage<N, KT>(A, Bw, m0, n0, kc + 1, sA[(kc + 1) & 1], sB[(kc + 1) & 1], tid);
            asm volatile("cp.async.wait_group 1;");
        } else {
            asm volatile("cp.async.wait_group 0;");
        }
        __syncthreads();

        const int st = kc & 1;
#pragma unroll
        for (int ks = 0; ks < 3; ks++) {
            uint32_t af[2][4], bf[3][2];
            const int arow0 = wr * 32 + (lane & 7) + ((lane >> 3) & 1) * 8;
            const int achk  = ks * 2 + (lane >> 4);
#pragma unroll
            for (int mi = 0; mi < 2; mi++) {
                int row = arow0 + mi * 16;
                ldsm4(af[mi][0], af[mi][1], af[mi][2], af[mi][3],
                      smem_u32(&sA[st][row * 64 + ((achk ^ (row & 7)) * 8)]));
            }
            const int brow = ks * 16 + (lane & 7) + ((lane >> 3) & 1) * 8;
            {
                int chk = wc * 3 + (lane >> 4);
                ldsm4t(bf[0][0], bf[0][1], bf[1][0], bf[1][1],
                       smem_u32(&sB[st][brow * 64 + ((chk ^ (brow & 7)) * 8)]));
                int chk2 = wc * 3 + 2;
                ldsm2t(bf[2][0], bf[2][1],
                       smem_u32(&sB[st][brow * 64 + ((chk2 ^ (brow & 7)) * 8)]));
            }
#pragma unroll
            for (int mi = 0; mi < 2; mi++)
#pragma unroll
                for (int ni = 0; ni < 3; ni++)
                    mma_f16(acc[mi][ni], af[mi], bf[ni]);
        }
        __syncthreads();
    }

    // ---------------- epilogue ----------------
    float ssum = 0.f;
#pragma unroll
    for (int mi = 0; mi < 2; mi++)
#pragma unroll
        for (int ni = 0; ni < 3; ni++) {
            int r = m0 + wr * 32 + mi * 16 + (lane >> 2);
            int c = n0 + wc * 24 + ni * 8 + 2 * (lane & 3);
            float v0 = acc[mi][ni][0], v1 = acc[mi][ni][1];
            float v2 = acc[mi][ni][2], v3 = acc[mi][ni][3];
            if (EPI == 0) {
                float b0 = bias[c], b1 = bias[c + 1];
                v0 += b0; v1 += b1; v2 += b0; v3 += b1;
                if (n0 < 192) ssum += v0 * v0 + v1 * v1 + v2 * v2 + v3 * v3;
                int s = c / 96, hd = (c % 96) >> 5, dd = c & 31;
                __half* dst = (s == 0) ? g_q_h : (s == 1) ? g_k_h : g_v_h;
                int w = r / NTOK, n = r % NTOK;
                *(uint32_t*)&dst[((size_t)(w * 3 + hd) * NTOK + n) * 32 + dd] = pack_h2(v0, v1);
                int r2 = r + 8; w = r2 / NTOK; n = r2 % NTOK;
                *(uint32_t*)&dst[((size_t)(w * 3 + hd) * NTOK + n) * 32 + dd] = pack_h2(v2, v3);
            } else if (EPI == 1) {
                float b0 = bias[c], b1 = bias[c + 1];
#pragma unroll
                for (int e = 0; e < 4; e++) {
                    int rr = r + (e >> 1) * 8;
                    int cc = c + (e & 1);
                    float val = ((e == 0) ? v0 : (e == 1) ? v1 : (e == 2) ? v2 : v3) +
                                ((e & 1) ? b1 : b0);
                    int w = rr / NTOK, n = rr % NTOK;
                    int b = w >> 6, wi = w & 63;
                    int Y = (wi >> 3) * WIN + n / WIN + SHIFTW; if (Y >= HWDIM) Y -= HWDIM;
                    int X = (wi & 7)  * WIN + n % WIN + SHIFTW; if (X >= HWDIM) X -= HWDIM;
                    size_t oi = ((size_t)b * (HWDIM * HWDIM) + Y * HWDIM + X) * CCH + cc;
                    out[oi] = Xres[oi] + val;
                }
            } else if (EPI == 2) {
                float b0 = bias[c], b1 = bias[c + 1];
                *(uint32_t*)&g_hid_h[(size_t)r * MLPH + c] =
                    pack_h2(gelu_tanh(v0 + b0), gelu_tanh(v1 + b1));
                *(uint32_t*)&g_hid_h[(size_t)(r + 8) * MLPH + c] =
                    pack_h2(gelu_tanh(v2 + b0), gelu_tanh(v3 + b1));
            } else {
                float b0 = bias[c], b1 = bias[c + 1];
                out[(size_t)r * CCH + c]           += v0 + b0;
                out[(size_t)r * CCH + c + 1]       += v1 + b1;
                out[(size_t)(r + 8) * CCH + c]     += v2 + b0;
                out[(size_t)(r + 8) * CCH + c + 1] += v3 + b1;
            }
        }

    if (EPI == 0) {
        ssum = warp_sum(ssum);
        if ((tid & 31) == 0) red[wid] = ssum;
        __syncthreads();
        if (tid == 0 && n0 < 192) {
            float t = 0.f;
#pragma unroll
            for (int i = 0; i < 8; i++) t += red[i];
            if (n0 < 96) g_pq[blockIdx.y * 2 + blockIdx.x] = t;
            else         g_pk[blockIdx.y * 2 + (blockIdx.x - 2)] = t;
        }
    }
}

// ---------------------------------------------------------------------------
// Final deterministic reduction of per-block partials
// ---------------------------------------------------------------------------
__global__ __launch_bounds__(256) void redfinal_kernel() {
    float lq = 0.f, lk = 0.f;
    for (int i = threadIdx.x; i < 3136; i += 256) { lq += g_pq[i]; lk += g_pk[i]; }
    lq = warp_sum(lq); lk = warp_sum(lk);
    __shared__ float sq8[8], sk8[8];
    if ((threadIdx.x & 31) == 0) { sq8[threadIdx.x >> 5] = lq; sk8[threadIdx.x >> 5] = lk; }
    __syncthreads();
    if (threadIdx.x == 0) {
        float a = 0.f, b = 0.f;
#pragma unroll
        for (int i = 0; i < 8; i++) { a += sq8[i]; b += sk8[i]; }
        g_sumq = a; g_sumk = b;
    }
}

// ---------------------------------------------------------------------------
// Attention: one block per (window, head). fp32 math, fp16 I/O.
// ---------------------------------------------------------------------------
__global__ __launch_bounds__(256) void attn_kernel(const float* __restrict__ tau) {
    __shared__ float sq[64 * 33];
    __shared__ float sk[64 * 33];
    __shared__ float sv[49 * 36];
    __shared__ float ss[49 * 49];
    __shared__ int   sreg[49];

    const int blk = blockIdx.x;
    const int w = blk / NHEADS, hd = blk % NHEADS;
    const int tid = threadIdx.x;
    const size_t base = (size_t)(w * NHEADS + hd) * NTOK * DHEAD;

    for (int idx = tid; idx < 64 * DHEAD; idx += 256) {
        int n = idx >> 5, dd = idx & 31;
        float qv = 0.f, kv = 0.f;
        if (n < NTOK) { qv = __half2float(g_q_h[base + idx]); kv = __half2float(g_k_h[base + idx]); }
        sq[n * 33 + dd] = qv;
        sk[n * 33 + dd] = kv;
    }
    for (int idx = tid; idx < NTOK * DHEAD; idx += 256) {
        int n = idx >> 5, dd = idx & 31;
        sv[n * 36 + dd] = __half2float(g_v_h[base + idx]);
    }
    if (tid < NTOK) {
        int wi = w & 63;
        int y = (wi >> 3) * WIN + tid / WIN;
        int x = (wi & 7)  * WIN + tid % WIN;
        int ry = (y < 49) ? 0 : ((y < 53) ? 1 : 2);
        int rx = (x < 49) ? 0 : ((x < 53) ? 1 : 2);
        sreg[tid] = ry * 3 + rx;
    }
    __syncthreads();

    const float scale = rsqrtf(g_sumq) * rsqrtf(g_sumk) / fmaxf(tau[0], 0.01f);

    {
        const int tj = tid & 15, ti = tid >> 4;
        float acc[4][4];
#pragma unroll
        for (int a = 0; a < 4; a++)
#pragma unroll
            for (int b = 0; b < 4; b++) acc[a][b] = 0.f;
#pragma unroll 8
        for (int kk = 0; kk < DHEAD; kk++) {
            float a0 = sq[(ti +  0) * 33 + kk];
            float a1 = sq[(ti + 16) * 33 + kk];
            float a2 = sq[(ti + 32) * 33 + kk];
            float a3 = sq[(ti + 48) * 33 + kk];
            float b0 = sk[(tj * 4 + 0) * 33 + kk];
            float b1 = sk[(tj * 4 + 1) * 33 + kk];
            float b2 = sk[(tj * 4 + 2) * 33 + kk];
            float b3 = sk[(tj * 4 + 3) * 33 + kk];
            acc[0][0] += a0 * b0; acc[0][1] += a0 * b1; acc[0][2] += a0 * b2; acc[0][3] += a0 * b3;
            acc[1][0] += a1 * b0; acc[1][1] += a1 * b1; acc[1][2] += a1 * b2; acc[1][3] += a1 * b3;
            acc[2][0] += a2 * b0; acc[2][1] += a2 * b1; acc[2][2] += a2 * b2; acc[2][3] += a2 * b3;
            acc[3][0] += a3 * b0; acc[3][1] += a3 * b1; acc[3][2] += a3 * b2; acc[3][3] += a3 * b3;
        }
        const float* bh = g_bias + hd * NTOK * NTOK;
#pragma unroll
        for (int a = 0; a < 4; a++) {
            int i = ti + 16 * a;
            if (i < NTOK) {
                int ri = sreg[i];
#pragma unroll
                for (int b = 0; b < 4; b++) {
                    int j = tj * 4 + b;
                    if (j < NTOK) {
                        float v = acc[a][b] * scale + bh[i * NTOK + j];
                        if (sreg[j] != ri) v -= 100.f;
                        ss[i * NTOK + j] = v;
                    }
                }
            }
        }
    }
    __syncthreads();

    {
        const int lane = tid & 31, wd = tid >> 5;
        for (int i = wd; i < NTOK; i += 8) {
            float v1 = (lane      < NTOK) ? ss[i * NTOK + lane]      : -1e30f;
            float v2 = (lane + 32 < NTOK) ? ss[i * NTOK + lane + 32] : -1e30f;
            float m = warp_max(fmaxf(v1, v2));
            float e1 = (lane      < NTOK) ? __expf(v1 - m) : 0.f;
            float e2 = (lane + 32 < NTOK) ? __expf(v2 - m) : 0.f;
            float s = warp_sum(e1 + e2);
            float inv = 1.f / s;
            if (lane      < NTOK) ss[i * NTOK + lane]      = e1 * inv;
            if (lane + 32 < NTOK) ss[i * NTOK + lane + 32] = e2 * inv;
        }
    }
    __syncthreads();

    {
        const int tc2 = tid & 3, tr2 = tid >> 2;
        if (tr2 < NTOK) {
            const int dd0 = tc2 * 8;
            float o0 = 0.f, o1 = 0.f, o2 = 0.f, o3 = 0.f;
            float o4 = 0.f, o5 = 0.f, o6 = 0.f, o7 = 0.f;
#pragma unroll 7
            for (int j = 0; j < NTOK; j++) {
                float p = ss[tr2 * NTOK + j];
                const float4 va = *reinterpret_cast<const float4*>(sv + j * 36 + dd0);
                const float4 vb = *reinterpret_cast<const float4*>(sv + j * 36 + dd0 + 4);
                o0 += p * va.x; o1 += p * va.y; o2 += p * va.z; o3 += p * va.w;
                o4 += p * vb.x; o5 += p * vb.y; o6 += p * vb.z; o7 += p * vb.w;
            }
            size_t ob = ((size_t)(w * NTOK + tr2)) * CCH + hd * DHEAD + dd0;
            uint32_t* dst = (uint32_t*)&g_o_h[ob];
            dst[0] = pack_h2(o0, o1);
            dst[1] = pack_h2(o2, o3);
            dst[2] = pack_h2(o4, o5);
            dst[3] = pack_h2(o6, o7);
        }
    }
}

// ---------------------------------------------------------------------------
// Launch (only harness pointers cross the host/device boundary)
// ---------------------------------------------------------------------------
extern "C" void kernel_launch(void* const* d_in, const int* in_sizes, int n_in,
                              void* d_out, int out_size) {
    const float* x      = (const float*)d_in[0];
    const float* n1g    = (const float*)d_in[1];
    const float* n1b    = (const float*)d_in[2];
    const float* qkv_w  = (const float*)d_in[3];
    const float* qkv_b  = (const float*)d_in[4];
    const float* proj_w = (const float*)d_in[5];
    const float* proj_b = (const float*)d_in[6];
    const float* mw1    = (const float*)d_in[7];
    const float* mb1    = (const float*)d_in[8];
    const float* mw2    = (const float*)d_in[9];
    const float* mb2    = (const float*)d_in[10];
    const float* tau    = (const float*)d_in[11];
    const float* n2g    = (const float*)d_in[12];
    const float* n2b    = (const float*)d_in[13];
    const float* fc1w   = (const float*)d_in[14];
    const float* fc1b   = (const float*)d_in[15];
    const float* fc2w   = (const float*)d_in[16];
    const float* fc2b   = (const float*)d_in[17];
    float* out = (float*)d_out;

    convw_kernel<<<432, 256>>>(qkv_w, proj_w, fc1w, fc2w);
    prep_kernel<<<19, 128>>>(mw1, mb1, mw2, mb2);
    ln1_gather_kernel<<<TOKENS / 8, 256>>>(x, n1g, n1b);

    hgemm_kernel<0><<<dim3(6, TOKENS / 128), 256>>>(qkv_b, nullptr, nullptr);
    redfinal_kernel<<<1, 256>>>();

    attn_kernel<<<NWTOT * NHEADS, 256>>>(tau);

    hgemm_kernel<1><<<dim3(2, TOKENS / 128), 256>>>(proj_b, x, out);

    ln2_kernel<<<TOKENS / 8, 256>>>(out, n2g, n2b);
    hgemm_kernel<2><<<dim3(8, TOKENS / 128), 256>>>(fc1b, nullptr, nullptr);
    hgemm_kernel<3><<<dim3(2, TOKENS / 128), 256>>>(fc2b, nullptr, out);
}

// round 6
// speedup vs baseline: 3.9151x; 1.4080x over previous
#include <cuda_runtime.h>
#include <cuda_fp16.h>
#include <cstdint>

// ---------------------------------------------------------------------------
// Problem constants
// ---------------------------------------------------------------------------
#define BIMG   64
#define HWDIM  56
#define CCH    96
#define NHEADS 3
#define DHEAD  32
#define WIN    7
#define SHIFTW 3
#define NTOK   49
#define NWIN   64
#define NWTOT  (BIMG * NWIN)      // 4096
#define TOKENS (NWTOT * NTOK)     // 200704
#define MLPH   384
#define METAH  128
#define LN_EPS 1e-5f

// ---------------------------------------------------------------------------
// Device scratch (static; cudaMalloc forbidden)
// ---------------------------------------------------------------------------
__device__ __align__(16) __half g_h_h  [(size_t)TOKENS * CCH];
__device__ __align__(16) __half g_q_h  [(size_t)TOKENS * CCH];
__device__ __align__(16) __half g_k_h  [(size_t)TOKENS * CCH];
__device__ __align__(16) __half g_v_h  [(size_t)TOKENS * CCH];
__device__ __align__(16) __half g_o_h  [(size_t)TOKENS * CCH];
__device__ __align__(16) __half g_ln2_h[(size_t)TOKENS * CCH];
__device__ __align__(16) __half g_hid_h[(size_t)TOKENS * MLPH];
__device__ __align__(16) __half g_wqkv [96 * 288];
__device__ __align__(16) __half g_wproj[96 * 96];
__device__ __align__(16) __half g_wfc1 [96 * 384];
__device__ __align__(16) __half g_wfc2 [384 * 96];
__device__ float g_bias[NHEADS * NTOK * NTOK];
__device__ float g_pq[3136], g_pk[3136];
__device__ float g_sumq, g_sumk;

// ---------------------------------------------------------------------------
// Helpers
// ---------------------------------------------------------------------------
__device__ __forceinline__ float warp_sum(float v) {
#pragma unroll
    for (int o = 16; o; o >>= 1) v += __shfl_xor_sync(0xffffffffu, v, o);
    return v;
}
__device__ __forceinline__ float gelu_tanh(float x) {
    float x3 = x * x * x;
    return 0.5f * x * (1.f + tanhf(0.7978845608028654f * (x + 0.044715f * x3)));
}
__device__ __forceinline__ uint32_t smem_u32(const void* p) {
    return (uint32_t)__cvta_generic_to_shared(p);
}
__device__ __forceinline__ void cp16(uint32_t dst, const void* src) {
    asm volatile("cp.async.cg.shared.global [%0], [%1], 16;" :: "r"(dst), "l"(src));
}
__device__ __forceinline__ void ldsm4(uint32_t& r0, uint32_t& r1, uint32_t& r2, uint32_t& r3, uint32_t a) {
    asm volatile("ldmatrix.sync.aligned.m8n8.x4.shared.b16 {%0,%1,%2,%3}, [%4];"
                 : "=r"(r0), "=r"(r1), "=r"(r2), "=r"(r3) : "r"(a));
}
__device__ __forceinline__ void ldsm4t(uint32_t& r0, uint32_t& r1, uint32_t& r2, uint32_t& r3, uint32_t a) {
    asm volatile("ldmatrix.sync.aligned.m8n8.x4.trans.shared.b16 {%0,%1,%2,%3}, [%4];"
                 : "=r"(r0), "=r"(r1), "=r"(r2), "=r"(r3) : "r"(a));
}
__device__ __forceinline__ void ldsm2t(uint32_t& r0, uint32_t& r1, uint32_t a) {
    asm volatile("ldmatrix.sync.aligned.m8n8.x2.trans.shared.b16 {%0,%1}, [%2];"
                 : "=r"(r0), "=r"(r1) : "r"(a));
}
__device__ __forceinline__ void mma_f16(float c[4], const uint32_t a[4], const uint32_t b[2]) {
    asm volatile(
        "mma.sync.aligned.m16n8k16.row.col.f32.f16.f16.f32 "
        "{%0,%1,%2,%3}, {%4,%5,%6,%7}, {%8,%9}, {%0,%1,%2,%3};"
        : "+f"(c[0]), "+f"(c[1]), "+f"(c[2]), "+f"(c[3])
        : "r"(a[0]), "r"(a[1]), "r"(a[2]), "r"(a[3]), "r"(b[0]), "r"(b[1]));
}
// pack two floats -> one u32 of two fp16, intrinsics only (no address-of-local)
__device__ __forceinline__ uint32_t pack_h2(float lo, float hi) {
    __half2 h = __floats2half2_rn(lo, hi);
    return (uint32_t)__half_as_ushort(__low2half(h)) |
           ((uint32_t)__half_as_ushort(__high2half(h)) << 16);
}

// ---------------------------------------------------------------------------
// Weight fp32 -> fp16 conversion (device code writing device symbols: legal)
// ---------------------------------------------------------------------------
__global__ void convw_kernel(const float* __restrict__ qkvw, const float* __restrict__ projw,
                             const float* __restrict__ fc1w, const float* __restrict__ fc2w) {
    int i = blockIdx.x * blockDim.x + threadIdx.x;
    if (i < 27648)            g_wqkv[i]          = __float2half_rn(qkvw[i]);
    else if (i < 36864)       g_wproj[i - 27648] = __float2half_rn(projw[i - 27648]);
    else if (i < 73728)       g_wfc1[i - 36864]  = __float2half_rn(fc1w[i - 36864]);
    else if (i < 110592)      g_wfc2[i - 73728]  = __float2half_rn(fc2w[i - 73728]);
}

// ---------------------------------------------------------------------------
// Prep: log-CPB bias table (3 x 49 x 49)
// ---------------------------------------------------------------------------
__global__ void prep_kernel(const float* __restrict__ w1, const float* __restrict__ b1,
                            const float* __restrict__ w2, const float* __restrict__ b2) {
    int idx = blockIdx.x * blockDim.x + threadIdx.x;
    if (idx >= NTOK * NTOK) return;
    int i = idx / NTOK, j = idx % NTOK;
    float d0 = (float)(i / WIN - j / WIN);
    float d1 = (float)(i % WIN - j % WIN);
    float r0 = copysignf(log1pf(fabsf(d0)), d0);
    float r1 = copysignf(log1pf(fabsf(d1)), d1);
    float a0 = 0.f, a1 = 0.f, a2 = 0.f;
#pragma unroll 4
    for (int m = 0; m < METAH; m++) {
        float hsum = r0 * w1[m] + r1 * w1[METAH + m] + b1[m];
        float gl = gelu_tanh(hsum);
        a0 += gl * w2[m * 3 + 0];
        a1 += gl * w2[m * 3 + 1];
        a2 += gl * w2[m * 3 + 2];
    }
    g_bias[0 * NTOK * NTOK + idx] = a0 + b2[0];
    g_bias[1 * NTOK * NTOK + idx] = a1 + b2[1];
    g_bias[2 * NTOK * NTOK + idx] = a2 + b2[2];
}

// ---------------------------------------------------------------------------
// LN1 + cyclic shift + window partition -> g_h_h (fp16). One warp per token.
// ---------------------------------------------------------------------------
__global__ __launch_bounds__(256) void ln1_gather_kernel(const float* __restrict__ x,
                                                         const float* __restrict__ g,
                                                         const float* __restrict__ b) {
    int warp = (blockIdx.x * blockDim.x + threadIdx.x) >> 5;
    int lane = threadIdx.x & 31;
    if (warp >= TOKENS) return;
    int w = warp / NTOK, n = warp % NTOK;
    int bimg = w >> 6, wi = w & 63;
    int Y = (wi >> 3) * WIN + n / WIN + SHIFTW; if (Y >= HWDIM) Y -= HWDIM;
    int X = (wi & 7)  * WIN + n % WIN + SHIFTW; if (X >= HWDIM) X -= HWDIM;
    const float* src = x + ((size_t)bimg * (HWDIM * HWDIM) + Y * HWDIM + X) * CCH;
    float v0 = src[lane], v1 = src[lane + 32], v2 = src[lane + 64];
    float s  = warp_sum(v0 + v1 + v2);
    float sq = warp_sum(v0 * v0 + v1 * v1 + v2 * v2);
    float mean = s * (1.f / CCH);
    float var  = sq * (1.f / CCH) - mean * mean;
    float inv  = rsqrtf(var + LN_EPS);
    __half* dst = g_h_h + (size_t)warp * CCH;
    dst[lane]      = __float2half_rn((v0 - mean) * inv * g[lane]      + b[lane]);
    dst[lane + 32] = __float2half_rn((v1 - mean) * inv * g[lane + 32] + b[lane + 32]);
    dst[lane + 64] = __float2half_rn((v2 - mean) * inv * g[lane + 64] + b[lane + 64]);
}

// ---------------------------------------------------------------------------
// LN2 over x2 (= d_out) -> g_ln2_h (fp16)
// ---------------------------------------------------------------------------
__global__ __launch_bounds__(256) void ln2_kernel(const float* __restrict__ x2,
                                                  const float* __restrict__ g,
                                                  const float* __restrict__ b) {
    int warp = (blockIdx.x * blockDim.x + threadIdx.x) >> 5;
    int lane = threadIdx.x & 31;
    if (warp >= TOKENS) return;
    const float* src = x2 + (size_t)warp * CCH;
    float v0 = src[lane], v1 = src[lane + 32], v2 = src[lane + 64];
    float s  = warp_sum(v0 + v1 + v2);
    float sq = warp_sum(v0 * v0 + v1 * v1 + v2 * v2);
    float mean = s * (1.f / CCH);
    float var  = sq * (1.f / CCH) - mean * mean;
    float inv  = rsqrtf(var + LN_EPS);
    __half* dst = g_ln2_h + (size_t)warp * CCH;
    dst[lane]      = __float2half_rn((v0 - mean) * inv * g[lane]      + b[lane]);
    dst[lane + 32] = __float2half_rn((v1 - mean) * inv * g[lane + 32] + b[lane + 32]);
    dst[lane + 64] = __float2half_rn((v2 - mean) * inv * g[lane + 64] + b[lane + 64]);
}

// ---------------------------------------------------------------------------
// GEMM stage loader (plain function: no lambda, no captured state)
// ---------------------------------------------------------------------------
template <int N, int KT>
__device__ __forceinline__ void gemm_load_stage(const __half* __restrict__ A,
                                                const __half* __restrict__ Bw,
                                                int m0, int n0, int kc,
                                                __half* sAst, __half* sBst, int tid) {
#pragma unroll
    for (int i = 0; i < 3; i++) {
        int idx = tid + i * 256;
        int r = idx / 6, c = idx - r * 6;
        const __half* src = A + (size_t)(m0 + r) * KT + kc * 48 + c * 8;
        cp16(smem_u32(sAst + r * 64 + ((c ^ (r & 7)) * 8)), src);
    }
#pragma unroll
    for (int i = 0; i < 2; i++) {
        int idx = tid + i * 256;
        if (idx < 288) {
            int r = idx / 6, c = idx - r * 6;
            const __half* src = Bw + (size_t)(kc * 48 + r) * N + n0 + c * 8;
            cp16(smem_u32(sBst + r * 64 + ((c ^ (r & 7)) * 8)), src);
        }
    }
    asm volatile("cp.async.commit_group;");
}

// ---------------------------------------------------------------------------
// fp16 tensor-core GEMM. BM=128, BN=48, BK=48, 2-stage cp.async pipeline,
// 8 warps (4m x 2n), warp tile 32x24 (2x3 m16n8k16), ldmatrix fragments.
// A and W selected IN-KERNEL from device symbols (never passed from host).
// ---------------------------------------------------------------------------
template <int EPI>
__global__ __launch_bounds__(256) void hgemm_kernel(const float* __restrict__ bias,
                                                    const float* __restrict__ Xres,
                                                    float* __restrict__ out) {
    constexpr int N   = (EPI == 0) ? 288 : (EPI == 2) ? 384 : 96;
    constexpr int KT  = (EPI == 3) ? 384 : 96;
    constexpr int NCH = KT / 48;
    const __half* __restrict__ A =
        (EPI == 0) ? g_h_h : (EPI == 1) ? g_o_h : (EPI == 2) ? g_ln2_h : g_hid_h;
    const __half* __restrict__ Bw =
        (EPI == 0) ? g_wqkv : (EPI == 1) ? g_wproj : (EPI == 2) ? g_wfc1 : g_wfc2;

    __shared__ __align__(16) __half sA[2][128 * 64];
    __shared__ __align__(16) __half sB[2][48 * 64];
    __shared__ float red[8];

    const int tid  = threadIdx.x;
    const int lane = tid & 31;
    const int wid  = tid >> 5;
    const int wr   = wid >> 1;
    const int wc   = wid & 1;
    const int n0   = blockIdx.x * 48;
    const int m0   = blockIdx.y * 128;

    float acc[2][3][4];
#pragma unroll
    for (int mi = 0; mi < 2; mi++)
#pragma unroll
        for (int ni = 0; ni < 3; ni++)
#pragma unroll
            for (int e = 0; e < 4; e++) acc[mi][ni][e] = 0.f;

    gemm_load_stage<N, KT>(A, Bw, m0, n0, 0, sA[0], sB[0], tid);

#pragma unroll 1
    for (int kc = 0; kc < NCH; kc++) {
        if (kc + 1 < NCH) {
            gemm_load_stage<N, KT>(A, Bw, m0, n0, kc + 1, sA[(kc + 1) & 1], sB[(kc + 1) & 1], tid);
            asm volatile("cp.async.wait_group 1;");
        } else {
            asm volatile("cp.async.wait_group 0;");
        }
        __syncthreads();

        const int st = kc & 1;
#pragma unroll
        for (int ks = 0; ks < 3; ks++) {
            uint32_t af[2][4], bf[3][2];
            const int arow0 = wr * 32 + (lane & 7) + ((lane >> 3) & 1) * 8;
            const int achk  = ks * 2 + (lane >> 4);
#pragma unroll
            for (int mi = 0; mi < 2; mi++) {
                int row = arow0 + mi * 16;
                ldsm4(af[mi][0], af[mi][1], af[mi][2], af[mi][3],
                      smem_u32(&sA[st][row * 64 + ((achk ^ (row & 7)) * 8)]));
            }
            const int brow = ks * 16 + (lane & 7) + ((lane >> 3) & 1) * 8;
            {
                int chk = wc * 3 + (lane >> 4);
                ldsm4t(bf[0][0], bf[0][1], bf[1][0], bf[1][1],
                       smem_u32(&sB[st][brow * 64 + ((chk ^ (brow & 7)) * 8)]));
                int chk2 = wc * 3 + 2;
                ldsm2t(bf[2][0], bf[2][1],
                       smem_u32(&sB[st][brow * 64 + ((chk2 ^ (brow & 7)) * 8)]));
            }
#pragma unroll
            for (int mi = 0; mi < 2; mi++)
#pragma unroll
                for (int ni = 0; ni < 3; ni++)
                    mma_f16(acc[mi][ni], af[mi], bf[ni]);
        }
        __syncthreads();
    }

    // ---------------- epilogue ----------------
    float ssum = 0.f;
#pragma unroll
    for (int mi = 0; mi < 2; mi++)
#pragma unroll
        for (int ni = 0; ni < 3; ni++) {
            int r = m0 + wr * 32 + mi * 16 + (lane >> 2);
            int c = n0 + wc * 24 + ni * 8 + 2 * (lane & 3);
            float v0 = acc[mi][ni][0], v1 = acc[mi][ni][1];
            float v2 = acc[mi][ni][2], v3 = acc[mi][ni][3];
            if (EPI == 0) {
                float b0 = bias[c], b1 = bias[c + 1];
                v0 += b0; v1 += b1; v2 += b0; v3 += b1;
                if (n0 < 192) ssum += v0 * v0 + v1 * v1 + v2 * v2 + v3 * v3;
                int s = c / 96, hd = (c % 96) >> 5, dd = c & 31;
                __half* dst = (s == 0) ? g_q_h : (s == 1) ? g_k_h : g_v_h;
                int w = r / NTOK, n = r % NTOK;
                *(uint32_t*)&dst[((size_t)(w * 3 + hd) * NTOK + n) * 32 + dd] = pack_h2(v0, v1);
                int r2 = r + 8; w = r2 / NTOK; n = r2 % NTOK;
                *(uint32_t*)&dst[((size_t)(w * 3 + hd) * NTOK + n) * 32 + dd] = pack_h2(v2, v3);
            } else if (EPI == 1) {
                float b0 = bias[c], b1 = bias[c + 1];
#pragma unroll
                for (int e = 0; e < 4; e++) {
                    int rr = r + (e >> 1) * 8;
                    int cc = c + (e & 1);
                    float val = ((e == 0) ? v0 : (e == 1) ? v1 : (e == 2) ? v2 : v3) +
                                ((e & 1) ? b1 : b0);
                    int w = rr / NTOK, n = rr % NTOK;
                    int b = w >> 6, wi = w & 63;
                    int Y = (wi >> 3) * WIN + n / WIN + SHIFTW; if (Y >= HWDIM) Y -= HWDIM;
                    int X = (wi & 7)  * WIN + n % WIN + SHIFTW; if (X >= HWDIM) X -= HWDIM;
                    size_t oi = ((size_t)b * (HWDIM * HWDIM) + Y * HWDIM + X) * CCH + cc;
                    out[oi] = Xres[oi] + val;
                }
            } else if (EPI == 2) {
                float b0 = bias[c], b1 = bias[c + 1];
                *(uint32_t*)&g_hid_h[(size_t)r * MLPH + c] =
                    pack_h2(gelu_tanh(v0 + b0), gelu_tanh(v1 + b1));
                *(uint32_t*)&g_hid_h[(size_t)(r + 8) * MLPH + c] =
                    pack_h2(gelu_tanh(v2 + b0), gelu_tanh(v3 + b1));
            } else {
                float b0 = bias[c], b1 = bias[c + 1];
                out[(size_t)r * CCH + c]           += v0 + b0;
                out[(size_t)r * CCH + c + 1]       += v1 + b1;
                out[(size_t)(r + 8) * CCH + c]     += v2 + b0;
                out[(size_t)(r + 8) * CCH + c + 1] += v3 + b1;
            }
        }

    if (EPI == 0) {
        ssum = warp_sum(ssum);
        if ((tid & 31) == 0) red[wid] = ssum;
        __syncthreads();
        if (tid == 0 && n0 < 192) {
            float t = 0.f;
#pragma unroll
            for (int i = 0; i < 8; i++) t += red[i];
            if (n0 < 96) g_pq[blockIdx.y * 2 + blockIdx.x] = t;
            else         g_pk[blockIdx.y * 2 + (blockIdx.x - 2)] = t;
        }
    }
}

// ---------------------------------------------------------------------------
// Final deterministic reduction of per-block partials
// ---------------------------------------------------------------------------
__global__ __launch_bounds__(256) void redfinal_kernel() {
    float lq = 0.f, lk = 0.f;
    for (int i = threadIdx.x; i < 3136; i += 256) { lq += g_pq[i]; lk += g_pk[i]; }
    lq = warp_sum(lq); lk = warp_sum(lk);
    __shared__ float sq8[8], sk8[8];
    if ((threadIdx.x & 31) == 0) { sq8[threadIdx.x >> 5] = lq; sk8[threadIdx.x >> 5] = lk; }
    __syncthreads();
    if (threadIdx.x == 0) {
        float a = 0.f, b = 0.f;
#pragma unroll
        for (int i = 0; i < 8; i++) { a += sq8[i]; b += sk8[i]; }
        g_sumq = a; g_sumk = b;
    }
}

// ---------------------------------------------------------------------------
// Attention v2: tensor cores. One block = (window, head), 128 threads/4 warps.
// Warp w owns S rows 16w..16w+15 (q tokens).  All matrices padded to 64 rows.
//  S = Q K^T : A = Q [m=49][k=32] row-major (ldsm4); B = K [n=49][k=32]
//              row-major == col-major of K^T (ldsm4, no trans).
//  softmax in accumulator registers (quad shfl reductions).
//  O = P V   : A = P fragments packed straight from S accumulators;
//              B = V [k=49][n=32] row-major (ldsm4t, like hgemm's B).
// ---------------------------------------------------------------------------
__global__ __launch_bounds__(128) void attn_kernel(const float* __restrict__ tau) {
    __shared__ __align__(16) __half sQ[64 * 40];   // pad 40 halves: ldsm conflict-free
    __shared__ __align__(16) __half sK[64 * 40];
    __shared__ __align__(16) __half sV[64 * 40];
    __shared__ float sbias[49 * 52];
    __shared__ int   sreg[64];

    const int blk  = blockIdx.x;
    const int w    = blk / NHEADS, hd = blk % NHEADS;
    const int tid  = threadIdx.x;
    const int lane = tid & 31, wid = tid >> 5;
    const size_t base = (size_t)(w * NHEADS + hd) * NTOK * DHEAD;   // halves

    // zero V (pad rows 49..63 must be 0.0, not junk: P*junk could be 0*NaN)
    for (int i = tid; i < 64 * 40 / 2; i += 128) ((uint32_t*)sV)[i] = 0u;
    __syncthreads();

    // load Q,K,V tiles: 49*32 halves = 196 uint4 each
    for (int i = tid; i < 196; i += 128) {
        int t = i >> 2, c = i & 3;       // token, 8-half chunk
        int o = t * 40 + c * 8;
        *(uint4*)(sQ + o) = *(const uint4*)(g_q_h + base + i * 8);
        *(uint4*)(sK + o) = *(const uint4*)(g_k_h + base + i * 8);
        *(uint4*)(sV + o) = *(const uint4*)(g_v_h + base + i * 8);
    }
    for (int i = tid; i < NTOK * NTOK; i += 128)
        sbias[(i / NTOK) * 52 + (i % NTOK)] = g_bias[hd * NTOK * NTOK + i];
    if (tid < NTOK) {
        int wi = w & 63;
        int y = (wi >> 3) * WIN + tid / WIN;
        int x = (wi & 7)  * WIN + tid % WIN;
        int ry = (y < 49) ? 0 : ((y < 53) ? 1 : 2);
        int rx = (x < 49) ? 0 : ((x < 53) ? 1 : 2);
        sreg[tid] = ry * 3 + rx;
    }
    __syncthreads();

    const float scale = rsqrtf(g_sumq) * rsqrtf(g_sumk) / fmaxf(tau[0], 0.01f);

    // ---- S = Q K^T : 8 n8-tiles x 2 k16-steps per warp ----
    float s[8][4];
#pragma unroll
    for (int t = 0; t < 8; t++)
#pragma unroll
        for (int e = 0; e < 4; e++) s[t][e] = 0.f;

#pragma unroll
    for (int ks = 0; ks < 2; ks++) {
        uint32_t av[4];
        {
            int arow = wid * 16 + (lane & 7) + ((lane >> 3) & 1) * 8;
            int achk = ks * 2 + (lane >> 4);
            ldsm4(av[0], av[1], av[2], av[3], smem_u32(sQ + arow * 40 + achk * 8));
        }
#pragma unroll
        for (int p = 0; p < 4; p++) {
            uint32_t b0, b1, b2, b3;
            int nrow = p * 16 + (lane & 7) + (lane >> 4) * 8;
            int kchk = ks * 2 + ((lane >> 3) & 1);
            ldsm4(b0, b1, b2, b3, smem_u32(sK + nrow * 40 + kchk * 8));
            uint32_t bp0[2] = {b0, b1};
            uint32_t bp1[2] = {b2, b3};
            mma_f16(s[2 * p],     av, bp0);
            mma_f16(s[2 * p + 1], av, bp1);
        }
    }

    // ---- scale + bias + shift-mask, softmax in registers ----
    const int r0 = wid * 16 + (lane >> 2);
    const int r1 = r0 + 8;
    const int jb = 2 * (lane & 3);
    const bool v0r = (r0 < NTOK), v1r = (r1 < NTOK);
    const int ri0 = sreg[v0r ? r0 : 0];
    const int ri1 = sreg[v1r ? r1 : 0];

    float m0 = -1e30f, m1 = -1e30f;
#pragma unroll
    for (int t = 0; t < 8; t++) {
#pragma unroll
        for (int e = 0; e < 2; e++) {
            int j = t * 8 + jb + e;
            bool jv = (j < NTOK);
            int rj = sreg[jv ? j : 0];
            float x0 = (v0r && jv)
                ? s[t][e] * scale + sbias[r0 * 52 + j] + ((rj != ri0) ? -100.f : 0.f)
                : -1e30f;
            float x1 = (v1r && jv)
                ? s[t][e + 2] * scale + sbias[r1 * 52 + j] + ((rj != ri1) ? -100.f : 0.f)
                : -1e30f;
            s[t][e] = x0; s[t][e + 2] = x1;
            m0 = fmaxf(m0, x0); m1 = fmaxf(m1, x1);
        }
    }
    m0 = fmaxf(m0, __shfl_xor_sync(0xffffffffu, m0, 1));
    m0 = fmaxf(m0, __shfl_xor_sync(0xffffffffu, m0, 2));
    m1 = fmaxf(m1, __shfl_xor_sync(0xffffffffu, m1, 1));
    m1 = fmaxf(m1, __shfl_xor_sync(0xffffffffu, m1, 2));

    float d0 = 0.f, d1 = 0.f;
#pragma unroll
    for (int t = 0; t < 8; t++) {
        float e0 = __expf(s[t][0] - m0), e1 = __expf(s[t][1] - m0);
        float e2 = __expf(s[t][2] - m1), e3 = __expf(s[t][3] - m1);
        s[t][0] = e0; s[t][1] = e1; s[t][2] = e2; s[t][3] = e3;
        d0 += e0 + e1; d1 += e2 + e3;
    }
    d0 += __shfl_xor_sync(0xffffffffu, d0, 1);
    d0 += __shfl_xor_sync(0xffffffffu, d0, 2);
    d1 += __shfl_xor_sync(0xffffffffu, d1, 1);
    d1 += __shfl_xor_sync(0xffffffffu, d1, 2);
    const float i0 = 1.f / d0, i1 = 1.f / d1;
#pragma unroll
    for (int t = 0; t < 8; t++) {
        s[t][0] *= i0; s[t][1] *= i0; s[t][2] *= i1; s[t][3] *= i1;
    }

    // ---- O = P V : P accumulators -> A fragments; V via trans ldsm ----
    float o[4][4];
#pragma unroll
    for (int v = 0; v < 4; v++)
#pragma unroll
        for (int e = 0; e < 4; e++) o[v][e] = 0.f;

#pragma unroll
    for (int kt = 0; kt < 4; kt++) {
        uint32_t av[4];
        av[0] = pack_h2(s[2 * kt][0],     s[2 * kt][1]);
        av[1] = pack_h2(s[2 * kt][2],     s[2 * kt][3]);
        av[2] = pack_h2(s[2 * kt + 1][0], s[2 * kt + 1][1]);
        av[3] = pack_h2(s[2 * kt + 1][2], s[2 * kt + 1][3]);
        int vrow = kt * 16 + (lane & 7) + ((lane >> 3) & 1) * 8;
#pragma unroll
        for (int half = 0; half < 2; half++) {
            uint32_t b0, b1, b2, b3;
            int vchk = half * 2 + (lane >> 4);
            ldsm4t(b0, b1, b2, b3, smem_u32(sV + vrow * 40 + vchk * 8));
            uint32_t bp0[2] = {b0, b1};
            uint32_t bp1[2] = {b2, b3};
            mma_f16(o[half * 2],     av, bp0);
            mma_f16(o[half * 2 + 1], av, bp1);
        }
    }

    // ---- store O rows < 49 to g_o_h [w*49 + r][hd*32 + col] ----
#pragma unroll
    for (int v = 0; v < 4; v++) {
        int col = hd * DHEAD + v * 8 + jb;
        if (v0r)
            *(uint32_t*)&g_o_h[(size_t)(w * NTOK + r0) * CCH + col] = pack_h2(o[v][0], o[v][1]);
        if (v1r)
            *(uint32_t*)&g_o_h[(size_t)(w * NTOK + r1) * CCH + col] = pack_h2(o[v][2], o[v][3]);
    }
}

// ---------------------------------------------------------------------------
// Launch (only harness pointers cross the host/device boundary)
// ---------------------------------------------------------------------------
extern "C" void kernel_launch(void* const* d_in, const int* in_sizes, int n_in,
                              void* d_out, int out_size) {
    const float* x      = (const float*)d_in[0];
    const float* n1g    = (const float*)d_in[1];
    const float* n1b    = (const float*)d_in[2];
    const float* qkv_w  = (const float*)d_in[3];
    const float* qkv_b  = (const float*)d_in[4];
    const float* proj_w = (const float*)d_in[5];
    const float* proj_b = (const float*)d_in[6];
    const float* mw1    = (const float*)d_in[7];
    const float* mb1    = (const float*)d_in[8];
    const float* mw2    = (const float*)d_in[9];
    const float* mb2    = (const float*)d_in[10];
    const float* tau    = (const float*)d_in[11];
    const float* n2g    = (const float*)d_in[12];
    const float* n2b    = (const float*)d_in[13];
    const float* fc1w   = (const float*)d_in[14];
    const float* fc1b   = (const float*)d_in[15];
    const float* fc2w   = (const float*)d_in[16];
    const float* fc2b   = (const float*)d_in[17];
    float* out = (float*)d_out;

    convw_kernel<<<432, 256>>>(qkv_w, proj_w, fc1w, fc2w);
    prep_kernel<<<19, 128>>>(mw1, mb1, mw2, mb2);
    ln1_gather_kernel<<<TOKENS / 8, 256>>>(x, n1g, n1b);

    hgemm_kernel<0><<<dim3(6, TOKENS / 128), 256>>>(qkv_b, nullptr, nullptr);
    redfinal_kernel<<<1, 256>>>();

    attn_kernel<<<NWTOT * NHEADS, 128>>>(tau);

    hgemm_kernel<1><<<dim3(2, TOKENS / 128), 256>>>(proj_b, x, out);

    ln2_kernel<<<TOKENS / 8, 256>>>(out, n2g, n2b);
    hgemm_kernel<2><<<dim3(8, TOKENS / 128), 256>>>(fc1b, nullptr, nullptr);
    hgemm_kernel<3><<<dim3(2, TOKENS / 128), 256>>>(fc2b, nullptr, out);
}